// round 7
// baseline (speedup 1.0000x reference)
#include <cuda_runtime.h>
#include <cuda_fp16.h>
#include <math.h>

#define N_NODES 100000
#define N_EDGES 1600000
#define NUSER   90000
#define NT2     (2 * NUSER)            // merged bucket count = 180000
#define SCAN_CHUNK 1024
#define NPART   ((NT2 + SCAN_CHUNK - 1) / SCAN_CHUNK)   // 176

#define GL   782      // hp-GEMM blocks per layer: ceil(100000/128)
#define UB   704      // u-GEMM blocks: ceil(90000/128)
#define HB   12500    // hist blocks: ceil(3.2M/256)
#define MEGA (2*GL + UB + HB)

// ---------------- scratch (device globals; zero-initialized at load) -------
__device__ __align__(16) __half g_hp0[N_NODES * 128];
__device__ __align__(16) __half g_hp1[N_NODES * 128];
__device__ __align__(16) float g_as [2 * N_NODES * 2];  // [layer][n*2+h]
__device__ __align__(16) float g_at [2 * N_NODES * 2];
__device__ __align__(16) float g_ta [NUSER  * 128];     // type_aware (n, k, d)
__device__ __align__(16) float g_u  [NUSER  * 64];
__device__ __align__(16) int   g_cnt[NT2];              // counts (reset by gather)
__device__ __align__(16) int   g_off[NT2];              // CSR offsets
__device__ __align__(16) int   g_cur[NT2];              // scatter cursors
__device__ __align__(16) int   g_part[256];
__device__ __align__(16) int   g_csr[2 * N_EDGES];      // bucketed src ids

// ---------------- hp GEMM body (one 128-row tile, one layer) ----------------
__device__ __forceinline__
void hp_gemm_tile(float* smem, int row0, int layer,
                  const float* __restrict__ A, const float* __restrict__ Braw,
                  const float* __restrict__ aS, const float* __restrict__ aT,
                  __half* __restrict__ hpL,
                  float* __restrict__ asOut, float* __restrict__ atOut, int M)
{
    constexpr int P   = 128;
    constexpr int BM  = 128;
    constexpr int LDA = BM + 4;
    float* As = smem;
    float* Bs = smem + 64 * LDA;
    const int t = threadIdx.x;

    #pragma unroll 4
    for (int i = t; i < 64 * P; i += 256) {
        int kk = i >> 7, c = i & 127;
        Bs[kk * P + c] = Braw[(c >> 6) * 4096 + kk * 64 + (c & 63)];
    }
    #pragma unroll 4
    for (int i = t; i < BM * 16; i += 256) {
        int r  = i >> 4;
        int k4 = (i & 15) << 2;
        float4 a = make_float4(0.f, 0.f, 0.f, 0.f);
        if (row0 + r < M) a = *(const float4*)(A + (size_t)(row0 + r) * 64 + k4);
        As[(k4 + 0) * LDA + r] = a.x;
        As[(k4 + 1) * LDA + r] = a.y;
        As[(k4 + 2) * LDA + r] = a.z;
        As[(k4 + 3) * LDA + r] = a.w;
    }
    __syncthreads();

    const int cg = t & 15;
    const int rg = t >> 4;

    float acc[8][8];
    #pragma unroll
    for (int r = 0; r < 8; r++)
        #pragma unroll
        for (int c = 0; c < 8; c++) acc[r][c] = 0.f;

    #pragma unroll
    for (int k = 0; k < 64; k++) {
        float4 a0 = *(const float4*)(As + k * LDA + rg * 8);
        float4 a1 = *(const float4*)(As + k * LDA + rg * 8 + 4);
        float a[8] = {a0.x, a0.y, a0.z, a0.w, a1.x, a1.y, a1.z, a1.w};
        float4 b0 = *(const float4*)(Bs + k * P + cg * 8);
        float4 b1 = *(const float4*)(Bs + k * P + cg * 8 + 4);
        float b[8] = {b0.x, b0.y, b0.z, b0.w, b1.x, b1.y, b1.z, b1.w};
        #pragma unroll
        for (int r = 0; r < 8; r++)
            #pragma unroll
            for (int c = 0; c < 8; c++)
                acc[r][c] = fmaf(a[r], b[c], acc[r][c]);
    }

    #pragma unroll
    for (int r = 0; r < 8; r++) {
        int row = row0 + rg * 8 + r;
        if (row < M) {
            union { __half2 h2[4]; uint4 u4; } pk;
            #pragma unroll
            for (int c2 = 0; c2 < 4; c2++)
                pk.h2[c2] = __floats2half2_rn(acc[r][2*c2], acc[r][2*c2+1]);
            *(uint4*)(hpL + (size_t)row * 128 + cg * 8) = pk.u4;
        }
    }

    float4 s0 = *(const float4*)(aS + cg * 8);
    float4 s1 = *(const float4*)(aS + cg * 8 + 4);
    float4 t0 = *(const float4*)(aT + cg * 8);
    float4 t1 = *(const float4*)(aT + cg * 8 + 4);
    float sv[8] = {s0.x, s0.y, s0.z, s0.w, s1.x, s1.y, s1.z, s1.w};
    float tv[8] = {t0.x, t0.y, t0.z, t0.w, t1.x, t1.y, t1.z, t1.w};

    float pas[8], pat[8];
    #pragma unroll
    for (int r = 0; r < 8; r++) {
        float a_ = 0.f, b_ = 0.f;
        #pragma unroll
        for (int c = 0; c < 8; c++) {
            a_ = fmaf(acc[r][c], sv[c], a_);
            b_ = fmaf(acc[r][c], tv[c], b_);
        }
        pas[r] = a_; pat[r] = b_;
    }
    #pragma unroll
    for (int o = 1; o < 8; o <<= 1) {
        #pragma unroll
        for (int r = 0; r < 8; r++) {
            pas[r] += __shfl_xor_sync(0xffffffffu, pas[r], o);
            pat[r] += __shfl_xor_sync(0xffffffffu, pat[r], o);
        }
    }
    if ((cg & 7) == 0) {
        int head  = cg >> 3;
        int abase = layer * N_NODES * 2;
        #pragma unroll
        for (int r = 0; r < 8; r++) {
            int row = row0 + rg * 8 + r;
            if (row < M) {
                asOut[abase + row * 2 + head] = pas[r];
                atOut[abase + row * 2 + head] = pat[r];
            }
        }
    }
}

// ---------------- P=64 transposed-B GEMM body (acc in registers) ------------
__device__ __forceinline__
void gemm64t_tile(float* smem, int row0,
                  const float* __restrict__ A, const float* __restrict__ Braw,
                  int M, float acc[8][4])
{
    constexpr int P   = 64;
    constexpr int BM  = 128;
    constexpr int LDA = BM + 4;
    float* As = smem;
    float* Bs = smem + 64 * LDA;
    const int t = threadIdx.x;

    #pragma unroll 4
    for (int i = t; i < 64 * P; i += 256) {
        int kk = i / P, c = i % P;
        Bs[kk * P + c] = Braw[c * 64 + kk];
    }
    #pragma unroll 4
    for (int i = t; i < BM * 16; i += 256) {
        int r  = i >> 4;
        int k4 = (i & 15) << 2;
        float4 a = make_float4(0.f, 0.f, 0.f, 0.f);
        if (row0 + r < M) a = *(const float4*)(A + (size_t)(row0 + r) * 64 + k4);
        As[(k4 + 0) * LDA + r] = a.x;
        As[(k4 + 1) * LDA + r] = a.y;
        As[(k4 + 2) * LDA + r] = a.z;
        As[(k4 + 3) * LDA + r] = a.w;
    }
    __syncthreads();

    const int cg = t & 15;
    const int rg = t >> 4;

    #pragma unroll
    for (int r = 0; r < 8; r++)
        #pragma unroll
        for (int c = 0; c < 4; c++) acc[r][c] = 0.f;

    #pragma unroll
    for (int k = 0; k < 64; k++) {
        float4 a0 = *(const float4*)(As + k * LDA + rg * 8);
        float4 a1 = *(const float4*)(As + k * LDA + rg * 8 + 4);
        float a[8] = {a0.x, a0.y, a0.z, a0.w, a1.x, a1.y, a1.z, a1.w};
        float4 b0 = *(const float4*)(Bs + k * P + cg * 4);
        float b[4] = {b0.x, b0.y, b0.z, b0.w};
        #pragma unroll
        for (int r = 0; r < 8; r++)
            #pragma unroll
            for (int c = 0; c < 4; c++)
                acc[r][c] = fmaf(a[r], b[c], acc[r][c]);
    }
}

// ---------------- MEGA: hp GEMM x2 + u GEMM + hist in one launch ------------
__global__ __launch_bounds__(256)
void mega_kernel(const float* __restrict__ h,
                 const float* __restrict__ W0, const float* __restrict__ W1,
                 const float* __restrict__ asrc0, const float* __restrict__ atrg0,
                 const float* __restrict__ asrc1, const float* __restrict__ atrg1,
                 __half* __restrict__ hp0, __half* __restrict__ hp1,
                 float* __restrict__ as_, float* __restrict__ at_,
                 const float* __restrict__ aaw1, float* __restrict__ u,
                 const int* __restrict__ trgA, const int* __restrict__ trgB,
                 int* __restrict__ cnt)
{
    extern __shared__ float smem[];
    int bx = blockIdx.x;

    if (bx < 2 * GL) {
        int layer = bx / GL;
        int row0  = (bx - layer * GL) * 128;
        hp_gemm_tile(smem, row0, layer, h,
                     layer ? W1 : W0,
                     layer ? asrc1 : asrc0,
                     layer ? atrg1 : atrg0,
                     layer ? hp1 : hp0, as_, at_, N_NODES);
        return;
    }
    if (bx < 2 * GL + UB) {
        int row0 = (bx - 2 * GL) * 128;
        float acc[8][4];
        gemm64t_tile(smem, row0, h, aaw1, NUSER, acc);
        const int cg = threadIdx.x & 15;
        const int rg = threadIdx.x >> 4;
        #pragma unroll
        for (int r = 0; r < 8; r++) {
            int row = row0 + rg * 8 + r;
            if (row < NUSER) {
                float4 o = make_float4(acc[r][0], acc[r][1], acc[r][2], acc[r][3]);
                *(float4*)(u + (size_t)row * 64 + cg * 4) = o;
            }
        }
        return;
    }
    // hist
    int i = (bx - 2 * GL - UB) * 256 + threadIdx.x;
    if (i >= 2 * N_EDGES) return;
    int layer = (i >= N_EDGES);
    const int* trg = layer ? trgB : trgA;
    int t = __ldg(trg + (i - layer * N_EDGES));
    if (t < NUSER) atomicAdd(cnt + layer * NUSER + t, 1);
}

// ---------------- scan 1: per-chunk exclusive scan ---------------------------
__global__ __launch_bounds__(256)
void scan1_kernel(const int* __restrict__ cnt, int* __restrict__ off,
                  int* __restrict__ part)
{
    __shared__ int s[256];
    int t = threadIdx.x, b = blockIdx.x;
    int i0 = b * SCAN_CHUNK + t * 4;
    int c[4];
    #pragma unroll
    for (int j = 0; j < 4; j++) c[j] = (i0 + j < NT2) ? cnt[i0 + j] : 0;
    int tot = c[0] + c[1] + c[2] + c[3];
    s[t] = tot;
    __syncthreads();
    int v = s[t];
    #pragma unroll
    for (int o = 1; o < 256; o <<= 1) {
        int u = (t >= o) ? s[t - o] : 0;
        __syncthreads();
        v += u; s[t] = v;
        __syncthreads();
    }
    int excl = v - tot;
    #pragma unroll
    for (int j = 0; j < 4; j++) {
        if (i0 + j < NT2) off[i0 + j] = excl;
        excl += c[j];
    }
    if (t == 255) part[b] = v;
}

// ---------------- scan 2+3 fused: add chunk base, init cursor ---------------
__global__ __launch_bounds__(256)
void scan23_kernel(int* __restrict__ off, const int* __restrict__ part,
                   int* __restrict__ cur)
{
    __shared__ int red[8];
    __shared__ int sbase;
    int b = blockIdx.x, t = threadIdx.x;
    int s = (t < b) ? part[t] : 0;       // NPART=176 < 256, single stride
    #pragma unroll
    for (int o = 16; o > 0; o >>= 1) s += __shfl_xor_sync(0xffffffffu, s, o);
    if ((t & 31) == 0) red[t >> 5] = s;
    __syncthreads();
    if (t == 0) {
        int v = 0;
        #pragma unroll
        for (int i = 0; i < 8; i++) v += red[i];
        sbase = v;
    }
    __syncthreads();
    int base = sbase;
    int i0 = b * SCAN_CHUNK + t * 4;
    #pragma unroll
    for (int j = 0; j < 4; j++) {
        int i = i0 + j;
        if (i < NT2) {
            int o = off[i] + base;
            off[i] = o;
            cur[i] = o;
        }
    }
}

__global__ __launch_bounds__(256)
void scatter_kernel(const int* __restrict__ srcA, const int* __restrict__ trgA,
                    const int* __restrict__ srcB, const int* __restrict__ trgB,
                    int* __restrict__ cur, int* __restrict__ csr)
{
    int i = blockIdx.x * blockDim.x + threadIdx.x;
    if (i >= 2 * N_EDGES) return;
    int layer = (i >= N_EDGES);
    int e = i - layer * N_EDGES;
    const int* trg = layer ? trgB : trgA;
    const int* src = layer ? srcB : srcA;
    int t = __ldg(trg + e);
    if (t >= NUSER) return;
    int pos = atomicAdd(cur + layer * NUSER + t, 1);
    csr[pos] = __ldg(src + e);
}

// ---------------- gather (R4 version) + cnt reset for next replay -----------
__global__ __launch_bounds__(256)
void gather_kernel(const int* __restrict__ csr, const int* __restrict__ off,
                   int* __restrict__ cnt,
                   const float* __restrict__ as_, const float* __restrict__ at_,
                   const __half* __restrict__ hp0, const __half* __restrict__ hp1,
                   float* __restrict__ ta)
{
    int w    = (blockIdx.x * blockDim.x + threadIdx.x) >> 5;
    int lane = threadIdx.x & 31;
    if (w >= NT2) return;
    int layer = (w >= NUSER);
    int t = w - layer * NUSER;
    const __half* hpL = layer ? hp1 : hp0;
    int abase = layer * N_NODES * 2;

    int grp  = lane >> 4;        // which edge of the pair
    int sub  = lane & 15;        // 16-lane slot within edge
    int hsel = sub >> 3;         // head of this lane

    float at_own = __ldg(at_ + abase + 2 * t + hsel);
    int start = __ldg(off + w);
    int n     = __ldg(cnt + w);
    if (lane == 0) cnt[w] = 0;   // reset for next graph replay (hist expects 0)

    float acc[8];
    #pragma unroll
    for (int j = 0; j < 8; j++) acc[j] = 0.f;
    float den = 0.f;

    for (int i = 0; i < n; i += 2) {
        int idx = i + grp;
        bool valid = idx < n;
        int sidx = valid ? idx : i;
        int s = __ldg(csr + start + sidx);
        float e = __ldg(as_ + abase + 2 * s + hsel) + at_own;
        e = (e > 0.f) ? e : 0.2f * e;
        float wgt = valid ? __expf(e) : 0.f;
        den += wgt;
        uint4 r = *(const uint4*)(hpL + (size_t)s * 128 + sub * 8);
        float2 f;
        f = __half22float2(*reinterpret_cast<__half2*>(&r.x));
        acc[0] = fmaf(wgt, f.x, acc[0]); acc[1] = fmaf(wgt, f.y, acc[1]);
        f = __half22float2(*reinterpret_cast<__half2*>(&r.y));
        acc[2] = fmaf(wgt, f.x, acc[2]); acc[3] = fmaf(wgt, f.y, acc[3]);
        f = __half22float2(*reinterpret_cast<__half2*>(&r.z));
        acc[4] = fmaf(wgt, f.x, acc[4]); acc[5] = fmaf(wgt, f.y, acc[5]);
        f = __half22float2(*reinterpret_cast<__half2*>(&r.w));
        acc[6] = fmaf(wgt, f.x, acc[6]); acc[7] = fmaf(wgt, f.y, acc[7]);
    }

    den += __shfl_xor_sync(0xffffffffu, den, 16);
    #pragma unroll
    for (int j = 0; j < 8; j++)
        acc[j] += __shfl_xor_sync(0xffffffffu, acc[j], 16);

    float inv = 1.f / (den + 1e-16f);
    #pragma unroll
    for (int j = 0; j < 8; j++) acc[j] *= inv;

    float other[8];
    #pragma unroll
    for (int j = 0; j < 8; j++)
        other[j] = __shfl_xor_sync(0xffffffffu, acc[j], 8);

    if (grp == 0 && hsel == 0) {
        float4 r0 = make_float4(0.5f * (acc[0] + other[0]), 0.5f * (acc[1] + other[1]),
                                0.5f * (acc[2] + other[2]), 0.5f * (acc[3] + other[3]));
        float4 r1 = make_float4(0.5f * (acc[4] + other[4]), 0.5f * (acc[5] + other[5]),
                                0.5f * (acc[6] + other[6]), 0.5f * (acc[7] + other[7]));
        float* dst = ta + (size_t)t * 128 + layer * 64 + sub * 8;
        *(float4*)(dst)     = r0;
        *(float4*)(dst + 4) = r1;
    }
}

// ---------------- vhead: v GEMM (smem-resident) + head fused ----------------
__global__ __launch_bounds__(256)
void vhead_kernel(const float* __restrict__ ta, const float* __restrict__ aaw2,
                  const float* __restrict__ u,
                  const float* __restrict__ aam, const float* __restrict__ fcw,
                  const float* __restrict__ fcb, float* __restrict__ outp)
{
    constexpr int LDA = 132;
    extern __shared__ float smem[];
    float* vbuf = smem + 64 * LDA + 64 * 64;   // [128][64] v tile

    int bx = blockIdx.x;
    int row0 = bx * 128;                        // v rows (= 2*user)

    float acc[8][4];
    gemm64t_tile(smem, row0, ta, aaw2, NT2, acc);

    const int cg = threadIdx.x & 15;
    const int rg = threadIdx.x >> 4;
    #pragma unroll
    for (int r = 0; r < 8; r++) {
        float4 o = make_float4(acc[r][0], acc[r][1], acc[r][2], acc[r][3]);
        *(float4*)(vbuf + (rg * 8 + r) * 64 + cg * 4) = o;
    }
    __syncthreads();

    // head for users [bx*64, bx*64+64)
    int u0 = bx * 64;
    int nu = NUSER - u0; if (nu > 64) nu = 64; if (nu < 0) nu = 0;
    int wib  = threadIdx.x >> 5;
    int lane = threadIdx.x & 31;
    int d1 = lane, d2 = lane + 32;

    float am1 = __ldg(aam + d1), am2 = __ldg(aam + d2);
    float fw01 = __ldg(fcw + d1),       fw02 = __ldg(fcw + d2);
    float fw11 = __ldg(fcw + 64 + d1),  fw12 = __ldg(fcw + 64 + d2);
    float fw21 = __ldg(fcw + 128 + d1), fw22 = __ldg(fcw + 128 + d2);
    float fw31 = __ldg(fcw + 192 + d1), fw32 = __ldg(fcw + 192 + d2);
    float fw41 = __ldg(fcw + 256 + d1), fw42 = __ldg(fcw + 256 + d2);
    float fw51 = __ldg(fcw + 320 + d1), fw52 = __ldg(fcw + 320 + d2);
    float b0c = __ldg(fcb + 0), b1c = __ldg(fcb + 1);

    for (int k = 0; k < 8; k++) {
        int ul = wib + 8 * k;
        if (ul >= nu) continue;
        int w = u0 + ul;

        float u1   = u[w * 64 + d1],          u2   = u[w * 64 + d2];
        float v01  = vbuf[(2*ul) * 64 + d1],  v02  = vbuf[(2*ul) * 64 + d2];
        float v11  = vbuf[(2*ul+1) * 64 + d1],v12  = vbuf[(2*ul+1) * 64 + d2];
        float ta01 = ta[w * 128 + d1],        ta02 = ta[w * 128 + d2];
        float ta11 = ta[w * 128 + 64 + d1],   ta12 = ta[w * 128 + 64 + d2];

        float s0 = tanhf(u1 + v01) * am1 + tanhf(u2 + v02) * am2;
        float s1 = tanhf(u1 + v11) * am1 + tanhf(u2 + v12) * am2;
        #pragma unroll
        for (int o = 16; o > 0; o >>= 1) {
            s0 += __shfl_xor_sync(0xffffffffu, s0, o);
            s1 += __shfl_xor_sync(0xffffffffu, s1, o);
        }
        float m  = fmaxf(s0, s1);
        float e0 = expf(s0 - m), e1 = expf(s1 - m);
        float rb = 1.f / (e0 + e1);
        float bb0 = e0 * rb, bb1 = e1 * rb;

        float f1 = bb0 * ta01 + bb1 * ta11;
        float f2 = bb0 * ta02 + bb1 * ta12;

        float l0 = ta01 * fw01 + ta02 * fw02 + ta11 * fw11 + ta12 * fw12
                 + f1 * fw21 + f2 * fw22;
        float l1 = ta01 * fw31 + ta02 * fw32 + ta11 * fw41 + ta12 * fw42
                 + f1 * fw51 + f2 * fw52;
        #pragma unroll
        for (int o = 16; o > 0; o >>= 1) {
            l0 += __shfl_xor_sync(0xffffffffu, l0, o);
            l1 += __shfl_xor_sync(0xffffffffu, l1, o);
        }
        if (lane == 0) {
            l0 += b0c;
            l1 += b1c;
            float mm  = fmaxf(l0, l1);
            float lse = mm + logf(expf(l0 - mm) + expf(l1 - mm));
            outp[w * 2]     = l0 - lse;
            outp[w * 2 + 1] = l1 - lse;
        }
    }
}

// ---------------- launch ----------------------------------------------------
extern "C" void kernel_launch(void* const* d_in, const int* in_sizes, int n_in,
                              void* d_out, int out_size)
{
    const float* h     = (const float*)d_in[0];
    const int*   src0  = (const int*)  d_in[1];
    const int*   trg0  = (const int*)  d_in[2];
    const int*   src1  = (const int*)  d_in[3];
    const int*   trg1  = (const int*)  d_in[4];
    const float* w0    = (const float*)d_in[5];
    const float* asrc0 = (const float*)d_in[6];
    const float* atrg0 = (const float*)d_in[7];
    const float* w1    = (const float*)d_in[8];
    const float* asrc1 = (const float*)d_in[9];
    const float* atrg1 = (const float*)d_in[10];
    const float* aaw1  = (const float*)d_in[11];
    const float* aaw2  = (const float*)d_in[12];
    const float* aam   = (const float*)d_in[13];
    const float* fcw   = (const float*)d_in[14];
    const float* fcb   = (const float*)d_in[15];
    float* out = (float*)d_out;

    __half *hp0, *hp1;
    float *as_, *at_, *ta, *u;
    int *cnt, *off, *cur, *part, *csr;
    cudaGetSymbolAddress((void**)&hp0,  g_hp0);
    cudaGetSymbolAddress((void**)&hp1,  g_hp1);
    cudaGetSymbolAddress((void**)&as_,  g_as);
    cudaGetSymbolAddress((void**)&at_,  g_at);
    cudaGetSymbolAddress((void**)&ta,   g_ta);
    cudaGetSymbolAddress((void**)&u,    g_u);
    cudaGetSymbolAddress((void**)&cnt,  g_cnt);
    cudaGetSymbolAddress((void**)&off,  g_off);
    cudaGetSymbolAddress((void**)&cur,  g_cur);
    cudaGetSymbolAddress((void**)&part, g_part);
    cudaGetSymbolAddress((void**)&csr,  g_csr);

    const int SM128 = (64 * 132 + 64 * 128) * 4;            // 66560 B
    const int SMVH  = (64 * 132 + 64 * 64 + 128 * 64) * 4;  // 82944 B
    cudaFuncSetAttribute(mega_kernel,  cudaFuncAttributeMaxDynamicSharedMemorySize, SM128);
    cudaFuncSetAttribute(vhead_kernel, cudaFuncAttributeMaxDynamicSharedMemorySize, SMVH);

    const int EDGE2_BLK = (2 * N_EDGES + 255) / 256;   // 12500
    const int GATH_BLK  = (NT2 * 32 + 255) / 256;      // 22500
    const int VH_BLK    = (NT2 + 127) / 128;           // 1407

    // 1. GEMMs (hp x2 + u) overlapped with hist
    mega_kernel<<<MEGA, 256, SM128>>>(h, w0, w1, asrc0, atrg0, asrc1, atrg1,
                                      hp0, hp1, as_, at_, aaw1, u,
                                      trg0, trg1, cnt);
    // 2-3. scans
    scan1_kernel<<<NPART, 256>>>(cnt, off, part);
    scan23_kernel<<<NPART, 256>>>(off, part, cur);
    // 4. scatter
    scatter_kernel<<<EDGE2_BLK, 256>>>(src0, trg0, src1, trg1, cur, csr);
    // 5. gather (also resets cnt for next replay)
    gather_kernel<<<GATH_BLK, 256>>>(csr, off, cnt, as_, at_, hp0, hp1, ta);
    // 6. v GEMM + head fused
    vhead_kernel<<<VH_BLK, 256, SMVH>>>(ta, aaw2, u, aam, fcw, fcb, out);

    (void)in_sizes; (void)n_in; (void)out_size;
}

// round 8
// speedup vs baseline: 1.2594x; 1.2594x over previous
#include <cuda_runtime.h>
#include <cuda_fp16.h>
#include <math.h>

#define N_NODES 100000
#define N_EDGES 1600000
#define NUSER   90000
#define NT2     (2 * NUSER)            // merged bucket count = 180000
#define SCAN_CHUNK 1024
#define NPART   ((NT2 + SCAN_CHUNK - 1) / SCAN_CHUNK)   // 176

#define GL   782      // hp-GEMM blocks per layer: ceil(100000/128)
#define UB   704      // u-GEMM blocks: ceil(90000/128)

// ---------------- scratch (device globals; zero-initialized at load) -------
__device__ __align__(16) __half g_hp0[N_NODES * 128];
__device__ __align__(16) __half g_hp1[N_NODES * 128];
__device__ __align__(16) float g_as [2 * N_NODES * 2];  // [layer][n*2+h]
__device__ __align__(16) float g_at [2 * N_NODES * 2];
__device__ __align__(16) float g_ta [NUSER  * 128];     // type_aware (n, k, d)
__device__ __align__(16) float g_u  [NUSER  * 64];
__device__ __align__(16) int   g_cnt[NT2];              // counts (reset by gather)
__device__ __align__(16) int   g_off[NT2];              // CSR offsets
__device__ __align__(16) int   g_cur[NT2];              // scatter cursors
__device__ __align__(16) int   g_part[256];
__device__ __align__(16) int   g_csr[2 * N_EDGES];      // bucketed src ids

// ---------------- hp GEMM body (one 128-row tile, one layer) ----------------
__device__ __forceinline__
void hp_gemm_tile(float* smem, int row0, int layer,
                  const float* __restrict__ A, const float* __restrict__ Braw,
                  const float* __restrict__ aS, const float* __restrict__ aT,
                  __half* __restrict__ hpL,
                  float* __restrict__ asOut, float* __restrict__ atOut, int M)
{
    constexpr int P   = 128;
    constexpr int BM  = 128;
    constexpr int LDA = BM + 4;
    float* As = smem;
    float* Bs = smem + 64 * LDA;
    const int t = threadIdx.x;

    #pragma unroll 4
    for (int i = t; i < 64 * P; i += 256) {
        int kk = i >> 7, c = i & 127;
        Bs[kk * P + c] = Braw[(c >> 6) * 4096 + kk * 64 + (c & 63)];
    }
    #pragma unroll 4
    for (int i = t; i < BM * 16; i += 256) {
        int r  = i >> 4;
        int k4 = (i & 15) << 2;
        float4 a = make_float4(0.f, 0.f, 0.f, 0.f);
        if (row0 + r < M) a = *(const float4*)(A + (size_t)(row0 + r) * 64 + k4);
        As[(k4 + 0) * LDA + r] = a.x;
        As[(k4 + 1) * LDA + r] = a.y;
        As[(k4 + 2) * LDA + r] = a.z;
        As[(k4 + 3) * LDA + r] = a.w;
    }
    __syncthreads();

    const int cg = t & 15;
    const int rg = t >> 4;

    float acc[8][8];
    #pragma unroll
    for (int r = 0; r < 8; r++)
        #pragma unroll
        for (int c = 0; c < 8; c++) acc[r][c] = 0.f;

    #pragma unroll
    for (int k = 0; k < 64; k++) {
        float4 a0 = *(const float4*)(As + k * LDA + rg * 8);
        float4 a1 = *(const float4*)(As + k * LDA + rg * 8 + 4);
        float a[8] = {a0.x, a0.y, a0.z, a0.w, a1.x, a1.y, a1.z, a1.w};
        float4 b0 = *(const float4*)(Bs + k * P + cg * 8);
        float4 b1 = *(const float4*)(Bs + k * P + cg * 8 + 4);
        float b[8] = {b0.x, b0.y, b0.z, b0.w, b1.x, b1.y, b1.z, b1.w};
        #pragma unroll
        for (int r = 0; r < 8; r++)
            #pragma unroll
            for (int c = 0; c < 8; c++)
                acc[r][c] = fmaf(a[r], b[c], acc[r][c]);
    }

    #pragma unroll
    for (int r = 0; r < 8; r++) {
        int row = row0 + rg * 8 + r;
        if (row < M) {
            union { __half2 h2[4]; uint4 u4; } pk;
            #pragma unroll
            for (int c2 = 0; c2 < 4; c2++)
                pk.h2[c2] = __floats2half2_rn(acc[r][2*c2], acc[r][2*c2+1]);
            *(uint4*)(hpL + (size_t)row * 128 + cg * 8) = pk.u4;
        }
    }

    float4 s0 = *(const float4*)(aS + cg * 8);
    float4 s1 = *(const float4*)(aS + cg * 8 + 4);
    float4 t0 = *(const float4*)(aT + cg * 8);
    float4 t1 = *(const float4*)(aT + cg * 8 + 4);
    float sv[8] = {s0.x, s0.y, s0.z, s0.w, s1.x, s1.y, s1.z, s1.w};
    float tv[8] = {t0.x, t0.y, t0.z, t0.w, t1.x, t1.y, t1.z, t1.w};

    float pas[8], pat[8];
    #pragma unroll
    for (int r = 0; r < 8; r++) {
        float a_ = 0.f, b_ = 0.f;
        #pragma unroll
        for (int c = 0; c < 8; c++) {
            a_ = fmaf(acc[r][c], sv[c], a_);
            b_ = fmaf(acc[r][c], tv[c], b_);
        }
        pas[r] = a_; pat[r] = b_;
    }
    #pragma unroll
    for (int o = 1; o < 8; o <<= 1) {
        #pragma unroll
        for (int r = 0; r < 8; r++) {
            pas[r] += __shfl_xor_sync(0xffffffffu, pas[r], o);
            pat[r] += __shfl_xor_sync(0xffffffffu, pat[r], o);
        }
    }
    if ((cg & 7) == 0) {
        int head  = cg >> 3;
        int abase = layer * N_NODES * 2;
        #pragma unroll
        for (int r = 0; r < 8; r++) {
            int row = row0 + rg * 8 + r;
            if (row < M) {
                asOut[abase + row * 2 + head] = pas[r];
                atOut[abase + row * 2 + head] = pat[r];
            }
        }
    }
}

// ---------------- P=64 transposed-B GEMM body (acc in registers) ------------
__device__ __forceinline__
void gemm64t_tile(float* smem, int row0,
                  const float* __restrict__ A, const float* __restrict__ Braw,
                  int M, float acc[8][4])
{
    constexpr int P   = 64;
    constexpr int BM  = 128;
    constexpr int LDA = BM + 4;
    float* As = smem;
    float* Bs = smem + 64 * LDA;
    const int t = threadIdx.x;

    #pragma unroll 4
    for (int i = t; i < 64 * P; i += 256) {
        int kk = i / P, c = i % P;
        Bs[kk * P + c] = Braw[c * 64 + kk];
    }
    #pragma unroll 4
    for (int i = t; i < BM * 16; i += 256) {
        int r  = i >> 4;
        int k4 = (i & 15) << 2;
        float4 a = make_float4(0.f, 0.f, 0.f, 0.f);
        if (row0 + r < M) a = *(const float4*)(A + (size_t)(row0 + r) * 64 + k4);
        As[(k4 + 0) * LDA + r] = a.x;
        As[(k4 + 1) * LDA + r] = a.y;
        As[(k4 + 2) * LDA + r] = a.z;
        As[(k4 + 3) * LDA + r] = a.w;
    }
    __syncthreads();

    const int cg = t & 15;
    const int rg = t >> 4;

    #pragma unroll
    for (int r = 0; r < 8; r++)
        #pragma unroll
        for (int c = 0; c < 4; c++) acc[r][c] = 0.f;

    #pragma unroll
    for (int k = 0; k < 64; k++) {
        float4 a0 = *(const float4*)(As + k * LDA + rg * 8);
        float4 a1 = *(const float4*)(As + k * LDA + rg * 8 + 4);
        float a[8] = {a0.x, a0.y, a0.z, a0.w, a1.x, a1.y, a1.z, a1.w};
        float4 b0 = *(const float4*)(Bs + k * P + cg * 4);
        float b[4] = {b0.x, b0.y, b0.z, b0.w};
        #pragma unroll
        for (int r = 0; r < 8; r++)
            #pragma unroll
            for (int c = 0; c < 4; c++)
                acc[r][c] = fmaf(a[r], b[c], acc[r][c]);
    }
}

// ---------------- merged GEMMs: hp x2 + u (all blocks use smem) -------------
__global__ __launch_bounds__(256)
void gemm_all_kernel(const float* __restrict__ h,
                     const float* __restrict__ W0, const float* __restrict__ W1,
                     const float* __restrict__ asrc0, const float* __restrict__ atrg0,
                     const float* __restrict__ asrc1, const float* __restrict__ atrg1,
                     __half* __restrict__ hp0, __half* __restrict__ hp1,
                     float* __restrict__ as_, float* __restrict__ at_,
                     const float* __restrict__ aaw1, float* __restrict__ u)
{
    extern __shared__ float smem[];
    int bx = blockIdx.x;

    if (bx < 2 * GL) {
        int layer = bx / GL;
        int row0  = (bx - layer * GL) * 128;
        hp_gemm_tile(smem, row0, layer, h,
                     layer ? W1 : W0,
                     layer ? asrc1 : asrc0,
                     layer ? atrg1 : atrg0,
                     layer ? hp1 : hp0, as_, at_, N_NODES);
        return;
    }
    // u GEMM
    int row0 = (bx - 2 * GL) * 128;
    float acc[8][4];
    gemm64t_tile(smem, row0, h, aaw1, NUSER, acc);
    const int cg = threadIdx.x & 15;
    const int rg = threadIdx.x >> 4;
    #pragma unroll
    for (int r = 0; r < 8; r++) {
        int row = row0 + rg * 8 + r;
        if (row < NUSER) {
            float4 o = make_float4(acc[r][0], acc[r][1], acc[r][2], acc[r][3]);
            *(float4*)(u + (size_t)row * 64 + cg * 4) = o;
        }
    }
}

// ---------------- hist: standalone, zero smem, full occupancy ---------------
__global__ __launch_bounds__(256)
void hist_kernel(const int* __restrict__ trgA, const int* __restrict__ trgB,
                 int* __restrict__ cnt)
{
    int i = blockIdx.x * blockDim.x + threadIdx.x;
    if (i >= 2 * N_EDGES) return;
    int layer = (i >= N_EDGES);
    const int* trg = layer ? trgB : trgA;
    int t = __ldg(trg + (i - layer * N_EDGES));
    if (t < NUSER) atomicAdd(cnt + layer * NUSER + t, 1);
}

// ---------------- scan 1: per-chunk exclusive scan ---------------------------
__global__ __launch_bounds__(256)
void scan1_kernel(const int* __restrict__ cnt, int* __restrict__ off,
                  int* __restrict__ part)
{
    __shared__ int s[256];
    int t = threadIdx.x, b = blockIdx.x;
    int i0 = b * SCAN_CHUNK + t * 4;
    int c[4];
    #pragma unroll
    for (int j = 0; j < 4; j++) c[j] = (i0 + j < NT2) ? cnt[i0 + j] : 0;
    int tot = c[0] + c[1] + c[2] + c[3];
    s[t] = tot;
    __syncthreads();
    int v = s[t];
    #pragma unroll
    for (int o = 1; o < 256; o <<= 1) {
        int u = (t >= o) ? s[t - o] : 0;
        __syncthreads();
        v += u; s[t] = v;
        __syncthreads();
    }
    int excl = v - tot;
    #pragma unroll
    for (int j = 0; j < 4; j++) {
        if (i0 + j < NT2) off[i0 + j] = excl;
        excl += c[j];
    }
    if (t == 255) part[b] = v;
}

// ---------------- scan 2+3 fused: add chunk base, init cursor ---------------
__global__ __launch_bounds__(256)
void scan23_kernel(int* __restrict__ off, const int* __restrict__ part,
                   int* __restrict__ cur)
{
    __shared__ int red[8];
    __shared__ int sbase;
    int b = blockIdx.x, t = threadIdx.x;
    int s = (t < b) ? part[t] : 0;       // NPART=176 < 256, single stride
    #pragma unroll
    for (int o = 16; o > 0; o >>= 1) s += __shfl_xor_sync(0xffffffffu, s, o);
    if ((t & 31) == 0) red[t >> 5] = s;
    __syncthreads();
    if (t == 0) {
        int v = 0;
        #pragma unroll
        for (int i = 0; i < 8; i++) v += red[i];
        sbase = v;
    }
    __syncthreads();
    int base = sbase;
    int i0 = b * SCAN_CHUNK + t * 4;
    #pragma unroll
    for (int j = 0; j < 4; j++) {
        int i = i0 + j;
        if (i < NT2) {
            int o = off[i] + base;
            off[i] = o;
            cur[i] = o;
        }
    }
}

__global__ __launch_bounds__(256)
void scatter_kernel(const int* __restrict__ srcA, const int* __restrict__ trgA,
                    const int* __restrict__ srcB, const int* __restrict__ trgB,
                    int* __restrict__ cur, int* __restrict__ csr)
{
    int i = blockIdx.x * blockDim.x + threadIdx.x;
    if (i >= 2 * N_EDGES) return;
    int layer = (i >= N_EDGES);
    int e = i - layer * N_EDGES;
    const int* trg = layer ? trgB : trgA;
    const int* src = layer ? srcB : srcA;
    int t = __ldg(trg + e);
    if (t >= NUSER) return;
    int pos = atomicAdd(cur + layer * NUSER + t, 1);
    csr[pos] = __ldg(src + e);
}

// ---------------- gather (R4 version) + cnt reset for next replay -----------
__global__ __launch_bounds__(256)
void gather_kernel(const int* __restrict__ csr, const int* __restrict__ off,
                   int* __restrict__ cnt,
                   const float* __restrict__ as_, const float* __restrict__ at_,
                   const __half* __restrict__ hp0, const __half* __restrict__ hp1,
                   float* __restrict__ ta)
{
    int w    = (blockIdx.x * blockDim.x + threadIdx.x) >> 5;
    int lane = threadIdx.x & 31;
    if (w >= NT2) return;
    int layer = (w >= NUSER);
    int t = w - layer * NUSER;
    const __half* hpL = layer ? hp1 : hp0;
    int abase = layer * N_NODES * 2;

    int grp  = lane >> 4;        // which edge of the pair
    int sub  = lane & 15;        // 16-lane slot within edge
    int hsel = sub >> 3;         // head of this lane

    float at_own = __ldg(at_ + abase + 2 * t + hsel);
    int start = __ldg(off + w);
    int n     = __ldg(cnt + w);
    if (lane == 0) cnt[w] = 0;   // reset for next graph replay (hist expects 0)

    float acc[8];
    #pragma unroll
    for (int j = 0; j < 8; j++) acc[j] = 0.f;
    float den = 0.f;

    for (int i = 0; i < n; i += 2) {
        int idx = i + grp;
        bool valid = idx < n;
        int sidx = valid ? idx : i;
        int s = __ldg(csr + start + sidx);
        float e = __ldg(as_ + abase + 2 * s + hsel) + at_own;
        e = (e > 0.f) ? e : 0.2f * e;
        float wgt = valid ? __expf(e) : 0.f;
        den += wgt;
        uint4 r = *(const uint4*)(hpL + (size_t)s * 128 + sub * 8);
        float2 f;
        f = __half22float2(*reinterpret_cast<__half2*>(&r.x));
        acc[0] = fmaf(wgt, f.x, acc[0]); acc[1] = fmaf(wgt, f.y, acc[1]);
        f = __half22float2(*reinterpret_cast<__half2*>(&r.y));
        acc[2] = fmaf(wgt, f.x, acc[2]); acc[3] = fmaf(wgt, f.y, acc[3]);
        f = __half22float2(*reinterpret_cast<__half2*>(&r.z));
        acc[4] = fmaf(wgt, f.x, acc[4]); acc[5] = fmaf(wgt, f.y, acc[5]);
        f = __half22float2(*reinterpret_cast<__half2*>(&r.w));
        acc[6] = fmaf(wgt, f.x, acc[6]); acc[7] = fmaf(wgt, f.y, acc[7]);
    }

    den += __shfl_xor_sync(0xffffffffu, den, 16);
    #pragma unroll
    for (int j = 0; j < 8; j++)
        acc[j] += __shfl_xor_sync(0xffffffffu, acc[j], 16);

    float inv = 1.f / (den + 1e-16f);
    #pragma unroll
    for (int j = 0; j < 8; j++) acc[j] *= inv;

    float other[8];
    #pragma unroll
    for (int j = 0; j < 8; j++)
        other[j] = __shfl_xor_sync(0xffffffffu, acc[j], 8);

    if (grp == 0 && hsel == 0) {
        float4 r0 = make_float4(0.5f * (acc[0] + other[0]), 0.5f * (acc[1] + other[1]),
                                0.5f * (acc[2] + other[2]), 0.5f * (acc[3] + other[3]));
        float4 r1 = make_float4(0.5f * (acc[4] + other[4]), 0.5f * (acc[5] + other[5]),
                                0.5f * (acc[6] + other[6]), 0.5f * (acc[7] + other[7]));
        float* dst = ta + (size_t)t * 128 + layer * 64 + sub * 8;
        *(float4*)(dst)     = r0;
        *(float4*)(dst + 4) = r1;
    }
}

// ---------------- vhead: v GEMM (smem-resident) + head fused ----------------
__global__ __launch_bounds__(256)
void vhead_kernel(const float* __restrict__ ta, const float* __restrict__ aaw2,
                  const float* __restrict__ u,
                  const float* __restrict__ aam, const float* __restrict__ fcw,
                  const float* __restrict__ fcb, float* __restrict__ outp)
{
    constexpr int LDA = 132;
    extern __shared__ float smem[];
    float* vbuf = smem + 64 * LDA + 64 * 64;   // [128][64] v tile

    int bx = blockIdx.x;
    int row0 = bx * 128;                        // v rows (= 2*user)

    float acc[8][4];
    gemm64t_tile(smem, row0, ta, aaw2, NT2, acc);

    const int cg = threadIdx.x & 15;
    const int rg = threadIdx.x >> 4;
    #pragma unroll
    for (int r = 0; r < 8; r++) {
        float4 o = make_float4(acc[r][0], acc[r][1], acc[r][2], acc[r][3]);
        *(float4*)(vbuf + (rg * 8 + r) * 64 + cg * 4) = o;
    }
    __syncthreads();

    // head for users [bx*64, bx*64+64)
    int u0 = bx * 64;
    int nu = NUSER - u0; if (nu > 64) nu = 64; if (nu < 0) nu = 0;
    int wib  = threadIdx.x >> 5;
    int lane = threadIdx.x & 31;
    int d1 = lane, d2 = lane + 32;

    float am1 = __ldg(aam + d1), am2 = __ldg(aam + d2);
    float fw01 = __ldg(fcw + d1),       fw02 = __ldg(fcw + d2);
    float fw11 = __ldg(fcw + 64 + d1),  fw12 = __ldg(fcw + 64 + d2);
    float fw21 = __ldg(fcw + 128 + d1), fw22 = __ldg(fcw + 128 + d2);
    float fw31 = __ldg(fcw + 192 + d1), fw32 = __ldg(fcw + 192 + d2);
    float fw41 = __ldg(fcw + 256 + d1), fw42 = __ldg(fcw + 256 + d2);
    float fw51 = __ldg(fcw + 320 + d1), fw52 = __ldg(fcw + 320 + d2);
    float b0c = __ldg(fcb + 0), b1c = __ldg(fcb + 1);

    for (int k = 0; k < 8; k++) {
        int ul = wib + 8 * k;
        if (ul >= nu) continue;
        int w = u0 + ul;

        float u1   = u[w * 64 + d1],          u2   = u[w * 64 + d2];
        float v01  = vbuf[(2*ul) * 64 + d1],  v02  = vbuf[(2*ul) * 64 + d2];
        float v11  = vbuf[(2*ul+1) * 64 + d1],v12  = vbuf[(2*ul+1) * 64 + d2];
        float ta01 = ta[w * 128 + d1],        ta02 = ta[w * 128 + d2];
        float ta11 = ta[w * 128 + 64 + d1],   ta12 = ta[w * 128 + 64 + d2];

        float s0 = tanhf(u1 + v01) * am1 + tanhf(u2 + v02) * am2;
        float s1 = tanhf(u1 + v11) * am1 + tanhf(u2 + v12) * am2;
        #pragma unroll
        for (int o = 16; o > 0; o >>= 1) {
            s0 += __shfl_xor_sync(0xffffffffu, s0, o);
            s1 += __shfl_xor_sync(0xffffffffu, s1, o);
        }
        float m  = fmaxf(s0, s1);
        float e0 = expf(s0 - m), e1 = expf(s1 - m);
        float rb = 1.f / (e0 + e1);
        float bb0 = e0 * rb, bb1 = e1 * rb;

        float f1 = bb0 * ta01 + bb1 * ta11;
        float f2 = bb0 * ta02 + bb1 * ta12;

        float l0 = ta01 * fw01 + ta02 * fw02 + ta11 * fw11 + ta12 * fw12
                 + f1 * fw21 + f2 * fw22;
        float l1 = ta01 * fw31 + ta02 * fw32 + ta11 * fw41 + ta12 * fw42
                 + f1 * fw51 + f2 * fw52;
        #pragma unroll
        for (int o = 16; o > 0; o >>= 1) {
            l0 += __shfl_xor_sync(0xffffffffu, l0, o);
            l1 += __shfl_xor_sync(0xffffffffu, l1, o);
        }
        if (lane == 0) {
            l0 += b0c;
            l1 += b1c;
            float mm  = fmaxf(l0, l1);
            float lse = mm + logf(expf(l0 - mm) + expf(l1 - mm));
            outp[w * 2]     = l0 - lse;
            outp[w * 2 + 1] = l1 - lse;
        }
    }
}

// ---------------- launch ----------------------------------------------------
extern "C" void kernel_launch(void* const* d_in, const int* in_sizes, int n_in,
                              void* d_out, int out_size)
{
    const float* h     = (const float*)d_in[0];
    const int*   src0  = (const int*)  d_in[1];
    const int*   trg0  = (const int*)  d_in[2];
    const int*   src1  = (const int*)  d_in[3];
    const int*   trg1  = (const int*)  d_in[4];
    const float* w0    = (const float*)d_in[5];
    const float* asrc0 = (const float*)d_in[6];
    const float* atrg0 = (const float*)d_in[7];
    const float* w1    = (const float*)d_in[8];
    const float* asrc1 = (const float*)d_in[9];
    const float* atrg1 = (const float*)d_in[10];
    const float* aaw1  = (const float*)d_in[11];
    const float* aaw2  = (const float*)d_in[12];
    const float* aam   = (const float*)d_in[13];
    const float* fcw   = (const float*)d_in[14];
    const float* fcb   = (const float*)d_in[15];
    float* out = (float*)d_out;

    __half *hp0, *hp1;
    float *as_, *at_, *ta, *u;
    int *cnt, *off, *cur, *part, *csr;
    cudaGetSymbolAddress((void**)&hp0,  g_hp0);
    cudaGetSymbolAddress((void**)&hp1,  g_hp1);
    cudaGetSymbolAddress((void**)&as_,  g_as);
    cudaGetSymbolAddress((void**)&at_,  g_at);
    cudaGetSymbolAddress((void**)&ta,   g_ta);
    cudaGetSymbolAddress((void**)&u,    g_u);
    cudaGetSymbolAddress((void**)&cnt,  g_cnt);
    cudaGetSymbolAddress((void**)&off,  g_off);
    cudaGetSymbolAddress((void**)&cur,  g_cur);
    cudaGetSymbolAddress((void**)&part, g_part);
    cudaGetSymbolAddress((void**)&csr,  g_csr);

    const int SM128 = (64 * 132 + 64 * 128) * 4;            // 66560 B
    const int SMVH  = (64 * 132 + 64 * 64 + 128 * 64) * 4;  // 82944 B
    cudaFuncSetAttribute(gemm_all_kernel, cudaFuncAttributeMaxDynamicSharedMemorySize, SM128);
    cudaFuncSetAttribute(vhead_kernel,    cudaFuncAttributeMaxDynamicSharedMemorySize, SMVH);

    const int EDGE2_BLK = (2 * N_EDGES + 255) / 256;   // 12500
    const int GATH_BLK  = (NT2 * 32 + 255) / 256;      // 22500
    const int VH_BLK    = (NT2 + 127) / 128;           // 1407

    // 1. hist (no smem, full occupancy)
    hist_kernel<<<EDGE2_BLK, 256>>>(trg0, trg1, cnt);
    // 2. all dense GEMMs (hp x2 + u), homogeneous 65KB smem blocks
    gemm_all_kernel<<<2 * GL + UB, 256, SM128>>>(h, w0, w1, asrc0, atrg0,
                                                 asrc1, atrg1, hp0, hp1,
                                                 as_, at_, aaw1, u);
    // 3-4. scans
    scan1_kernel<<<NPART, 256>>>(cnt, off, part);
    scan23_kernel<<<NPART, 256>>>(off, part, cur);
    // 5. scatter
    scatter_kernel<<<EDGE2_BLK, 256>>>(src0, trg0, src1, trg1, cur, csr);
    // 6. gather (also resets cnt for next replay)
    gather_kernel<<<GATH_BLK, 256>>>(csr, off, cnt, as_, at_, hp0, hp1, ta);
    // 7. v GEMM + head fused
    vhead_kernel<<<VH_BLK, 256, SMVH>>>(ta, aaw2, u, aam, fcw, fcb, out);

    (void)in_sizes; (void)n_in; (void)out_size;
}

// round 9
// speedup vs baseline: 1.2930x; 1.0267x over previous
#include <cuda_runtime.h>
#include <cuda_fp16.h>
#include <math.h>

#define N_NODES 100000
#define N_EDGES 1600000
#define NUSER   90000
#define NT2     (2 * NUSER)            // merged bucket count = 180000
#define SCAN_CHUNK 1024
#define NPART   ((NT2 + SCAN_CHUNK - 1) / SCAN_CHUNK)   // 176
#define UB      704                    // u-GEMM blocks: ceil(90000/128)
#define VB      1407                   // v-GEMM blocks: ceil(180000/128)

// ---------------- scratch (device globals; zero-initialized at load) -------
__device__ __align__(16) __half g_hp0[N_NODES * 128];
__device__ __align__(16) __half g_hp1[N_NODES * 128];
__device__ __align__(16) float g_as [2 * N_NODES * 2];  // [layer][n*2+h]
__device__ __align__(16) float g_at [2 * N_NODES * 2];
__device__ __align__(16) float g_ta [NUSER  * 128];     // type_aware (n, k, d)
__device__ __align__(16) float g_u  [NUSER  * 64];
__device__ __align__(16) float g_v  [NUSER  * 128];
__device__ __align__(16) int   g_cnt[NT2];              // counts (reset by gather)
__device__ __align__(16) int   g_off[NT2];              // CSR offsets
__device__ __align__(16) int   g_cur[NT2];              // scatter cursors
__device__ __align__(16) int   g_part[256];
__device__ __align__(16) int   g_csr[2 * N_EDGES];      // bucketed src ids

// ---------------- fused hp GEMM + attn logits (exact R4) --------------------
__global__ __launch_bounds__(256)
void gemm_hp_fused(const float* __restrict__ A,
                   const float* __restrict__ W0, const float* __restrict__ W1,
                   const float* __restrict__ asrc0, const float* __restrict__ atrg0,
                   const float* __restrict__ asrc1, const float* __restrict__ atrg1,
                   __half* __restrict__ hp0, __half* __restrict__ hp1,
                   float* __restrict__ asOut, float* __restrict__ atOut, int M)
{
    constexpr int P   = 128;
    constexpr int BM  = 128;
    constexpr int LDA = BM + 4;

    const int layer = blockIdx.y;
    const float* Braw = layer ? W1 : W0;
    const float* aS   = layer ? asrc1 : asrc0;
    const float* aT   = layer ? atrg1 : atrg0;
    __half* hpL = layer ? hp1 : hp0;

    extern __shared__ float smem[];
    float* As = smem;                        // [64][LDA]
    float* Bs = smem + 64 * LDA;             // [64][128]

    const int t    = threadIdx.x;
    const int row0 = blockIdx.x * BM;

    #pragma unroll 4
    for (int i = t; i < 64 * P; i += 256) {
        int kk = i >> 7, c = i & 127;
        Bs[kk * P + c] = Braw[(c >> 6) * 4096 + kk * 64 + (c & 63)];
    }
    #pragma unroll 4
    for (int i = t; i < BM * 16; i += 256) {
        int r  = i >> 4;
        int k4 = (i & 15) << 2;
        float4 a = make_float4(0.f, 0.f, 0.f, 0.f);
        if (row0 + r < M) a = *(const float4*)(A + (size_t)(row0 + r) * 64 + k4);
        As[(k4 + 0) * LDA + r] = a.x;
        As[(k4 + 1) * LDA + r] = a.y;
        As[(k4 + 2) * LDA + r] = a.z;
        As[(k4 + 3) * LDA + r] = a.w;
    }
    __syncthreads();

    const int cg = t & 15;
    const int rg = t >> 4;

    float acc[8][8];
    #pragma unroll
    for (int r = 0; r < 8; r++)
        #pragma unroll
        for (int c = 0; c < 8; c++) acc[r][c] = 0.f;

    #pragma unroll
    for (int k = 0; k < 64; k++) {
        float4 a0 = *(const float4*)(As + k * LDA + rg * 8);
        float4 a1 = *(const float4*)(As + k * LDA + rg * 8 + 4);
        float a[8] = {a0.x, a0.y, a0.z, a0.w, a1.x, a1.y, a1.z, a1.w};
        float4 b0 = *(const float4*)(Bs + k * P + cg * 8);
        float4 b1 = *(const float4*)(Bs + k * P + cg * 8 + 4);
        float b[8] = {b0.x, b0.y, b0.z, b0.w, b1.x, b1.y, b1.z, b1.w};
        #pragma unroll
        for (int r = 0; r < 8; r++)
            #pragma unroll
            for (int c = 0; c < 8; c++)
                acc[r][c] = fmaf(a[r], b[c], acc[r][c]);
    }

    #pragma unroll
    for (int r = 0; r < 8; r++) {
        int row = row0 + rg * 8 + r;
        if (row < M) {
            union { __half2 h2[4]; uint4 u4; } pk;
            #pragma unroll
            for (int c2 = 0; c2 < 4; c2++)
                pk.h2[c2] = __floats2half2_rn(acc[r][2*c2], acc[r][2*c2+1]);
            *(uint4*)(hpL + (size_t)row * 128 + cg * 8) = pk.u4;
        }
    }

    float4 s0 = *(const float4*)(aS + cg * 8);
    float4 s1 = *(const float4*)(aS + cg * 8 + 4);
    float4 t0 = *(const float4*)(aT + cg * 8);
    float4 t1 = *(const float4*)(aT + cg * 8 + 4);
    float sv[8] = {s0.x, s0.y, s0.z, s0.w, s1.x, s1.y, s1.z, s1.w};
    float tv[8] = {t0.x, t0.y, t0.z, t0.w, t1.x, t1.y, t1.z, t1.w};

    float pas[8], pat[8];
    #pragma unroll
    for (int r = 0; r < 8; r++) {
        float a_ = 0.f, b_ = 0.f;
        #pragma unroll
        for (int c = 0; c < 8; c++) {
            a_ = fmaf(acc[r][c], sv[c], a_);
            b_ = fmaf(acc[r][c], tv[c], b_);
        }
        pas[r] = a_; pat[r] = b_;
    }
    #pragma unroll
    for (int o = 1; o < 8; o <<= 1) {
        #pragma unroll
        for (int r = 0; r < 8; r++) {
            pas[r] += __shfl_xor_sync(0xffffffffu, pas[r], o);
            pat[r] += __shfl_xor_sync(0xffffffffu, pat[r], o);
        }
    }
    if ((cg & 7) == 0) {
        int head  = cg >> 3;
        int abase = layer * N_NODES * 2;
        #pragma unroll
        for (int r = 0; r < 8; r++) {
            int row = row0 + rg * 8 + r;
            if (row < M) {
                asOut[abase + row * 2 + head] = pas[r];
                atOut[abase + row * 2 + head] = pat[r];
            }
        }
    }
}

// ---------------- head GEMMs, flat grid: [0,UB)->u ; [UB,UB+VB)->v ----------
__global__ __launch_bounds__(256)
void gemm_head(const float* __restrict__ A0, const float* __restrict__ B0,
               float* __restrict__ C0, int M0,
               const float* __restrict__ A1, const float* __restrict__ B1,
               float* __restrict__ C1, int M1)
{
    constexpr int P   = 64;
    constexpr int BM  = 128;
    constexpr int LDA = BM + 4;

    const int bx  = blockIdx.x;
    const int sel = (bx >= UB);
    const float* A    = sel ? A1 : A0;
    const float* Braw = sel ? B1 : B0;
    float*       C    = sel ? C1 : C0;
    const int    M    = sel ? M1 : M0;
    const int row0 = (sel ? (bx - UB) : bx) * BM;

    extern __shared__ float smem[];
    float* As = smem;
    float* Bs = smem + 64 * LDA;

    const int t = threadIdx.x;

    #pragma unroll 4
    for (int i = t; i < 64 * P; i += 256) {
        int kk = i / P, c = i % P;
        Bs[kk * P + c] = Braw[c * 64 + kk];
    }
    #pragma unroll 4
    for (int i = t; i < BM * 16; i += 256) {
        int r  = i >> 4;
        int k4 = (i & 15) << 2;
        float4 a = make_float4(0.f, 0.f, 0.f, 0.f);
        if (row0 + r < M) a = *(const float4*)(A + (size_t)(row0 + r) * 64 + k4);
        As[(k4 + 0) * LDA + r] = a.x;
        As[(k4 + 1) * LDA + r] = a.y;
        As[(k4 + 2) * LDA + r] = a.z;
        As[(k4 + 3) * LDA + r] = a.w;
    }
    __syncthreads();

    const int cg = t & 15;
    const int rg = t >> 4;

    float acc[8][4];
    #pragma unroll
    for (int r = 0; r < 8; r++)
        #pragma unroll
        for (int c = 0; c < 4; c++) acc[r][c] = 0.f;

    #pragma unroll
    for (int k = 0; k < 64; k++) {
        float4 a0 = *(const float4*)(As + k * LDA + rg * 8);
        float4 a1 = *(const float4*)(As + k * LDA + rg * 8 + 4);
        float a[8] = {a0.x, a0.y, a0.z, a0.w, a1.x, a1.y, a1.z, a1.w};
        float4 b0 = *(const float4*)(Bs + k * P + cg * 4);
        float b[4] = {b0.x, b0.y, b0.z, b0.w};
        #pragma unroll
        for (int r = 0; r < 8; r++)
            #pragma unroll
            for (int c = 0; c < 4; c++)
                acc[r][c] = fmaf(a[r], b[c], acc[r][c]);
    }

    #pragma unroll
    for (int r = 0; r < 8; r++) {
        int row = row0 + rg * 8 + r;
        if (row < M) {
            float4 o = make_float4(acc[r][0], acc[r][1], acc[r][2], acc[r][3]);
            *(float4*)(C + (size_t)row * P + cg * 4) = o;
        }
    }
}

// ---------------- CSR build --------------------------------------------------
__global__ __launch_bounds__(256)
void hist_kernel(const int* __restrict__ trgA, const int* __restrict__ trgB,
                 int* __restrict__ cnt)
{
    int i = blockIdx.x * blockDim.x + threadIdx.x;
    if (i >= 2 * N_EDGES) return;
    int layer = (i >= N_EDGES);
    const int* trg = layer ? trgB : trgA;
    int t = __ldg(trg + (i - layer * N_EDGES));
    if (t < NUSER) atomicAdd(cnt + layer * NUSER + t, 1);
}

__global__ __launch_bounds__(256)
void scan1_kernel(const int* __restrict__ cnt, int* __restrict__ off,
                  int* __restrict__ part)
{
    __shared__ int s[256];
    int t = threadIdx.x, b = blockIdx.x;
    int i0 = b * SCAN_CHUNK + t * 4;
    int c[4];
    #pragma unroll
    for (int j = 0; j < 4; j++) c[j] = (i0 + j < NT2) ? cnt[i0 + j] : 0;
    int tot = c[0] + c[1] + c[2] + c[3];
    s[t] = tot;
    __syncthreads();
    int v = s[t];
    #pragma unroll
    for (int o = 1; o < 256; o <<= 1) {
        int u = (t >= o) ? s[t - o] : 0;
        __syncthreads();
        v += u; s[t] = v;
        __syncthreads();
    }
    int excl = v - tot;
    #pragma unroll
    for (int j = 0; j < 4; j++) {
        if (i0 + j < NT2) off[i0 + j] = excl;
        excl += c[j];
    }
    if (t == 255) part[b] = v;
}

// ---------------- scan2+3 fused: add chunk base, init cursor ----------------
__global__ __launch_bounds__(256)
void scan23_kernel(int* __restrict__ off, const int* __restrict__ part,
                   int* __restrict__ cur)
{
    __shared__ int red[8];
    __shared__ int sbase;
    int b = blockIdx.x, t = threadIdx.x;
    int s = (t < b) ? part[t] : 0;       // NPART=176 < 256, single stride
    #pragma unroll
    for (int o = 16; o > 0; o >>= 1) s += __shfl_xor_sync(0xffffffffu, s, o);
    if ((t & 31) == 0) red[t >> 5] = s;
    __syncthreads();
    if (t == 0) {
        int v = 0;
        #pragma unroll
        for (int i = 0; i < 8; i++) v += red[i];
        sbase = v;
    }
    __syncthreads();
    int base = sbase;
    int i0 = b * SCAN_CHUNK + t * 4;
    #pragma unroll
    for (int j = 0; j < 4; j++) {
        int i = i0 + j;
        if (i < NT2) {
            int o = off[i] + base;
            off[i] = o;
            cur[i] = o;
        }
    }
}

__global__ __launch_bounds__(256)
void scatter_kernel(const int* __restrict__ srcA, const int* __restrict__ trgA,
                    const int* __restrict__ srcB, const int* __restrict__ trgB,
                    int* __restrict__ cur, int* __restrict__ csr)
{
    int i = blockIdx.x * blockDim.x + threadIdx.x;
    if (i >= 2 * N_EDGES) return;
    int layer = (i >= N_EDGES);
    int e = i - layer * N_EDGES;
    const int* trg = layer ? trgB : trgA;
    const int* src = layer ? srcB : srcA;
    int t = __ldg(trg + e);
    if (t >= NUSER) return;
    int pos = atomicAdd(cur + layer * NUSER + t, 1);
    csr[pos] = __ldg(src + e);
}

// ---------------- gather (exact R4) + cnt reset for next replay --------------
__global__ __launch_bounds__(256)
void gather_kernel(const int* __restrict__ csr, const int* __restrict__ off,
                   int* __restrict__ cnt,
                   const float* __restrict__ as_, const float* __restrict__ at_,
                   const __half* __restrict__ hp0, const __half* __restrict__ hp1,
                   float* __restrict__ ta)
{
    int w    = (blockIdx.x * blockDim.x + threadIdx.x) >> 5;
    int lane = threadIdx.x & 31;
    if (w >= NT2) return;
    int layer = (w >= NUSER);
    int t = w - layer * NUSER;
    const __half* hpL = layer ? hp1 : hp0;
    int abase = layer * N_NODES * 2;

    int grp  = lane >> 4;        // which edge of the pair
    int sub  = lane & 15;        // 16-lane slot within edge
    int hsel = sub >> 3;         // head of this lane

    float at_own = __ldg(at_ + abase + 2 * t + hsel);
    int start = __ldg(off + w);
    int n     = __ldg(cnt + w);
    if (lane == 0) cnt[w] = 0;   // reset for next graph replay (hist expects 0)

    float acc[8];
    #pragma unroll
    for (int j = 0; j < 8; j++) acc[j] = 0.f;
    float den = 0.f;

    for (int i = 0; i < n; i += 2) {
        int idx = i + grp;
        bool valid = idx < n;
        int sidx = valid ? idx : i;
        int s = __ldg(csr + start + sidx);
        float e = __ldg(as_ + abase + 2 * s + hsel) + at_own;
        e = (e > 0.f) ? e : 0.2f * e;
        float wgt = valid ? __expf(e) : 0.f;
        den += wgt;
        uint4 r = *(const uint4*)(hpL + (size_t)s * 128 + sub * 8);
        float2 f;
        f = __half22float2(*reinterpret_cast<__half2*>(&r.x));
        acc[0] = fmaf(wgt, f.x, acc[0]); acc[1] = fmaf(wgt, f.y, acc[1]);
        f = __half22float2(*reinterpret_cast<__half2*>(&r.y));
        acc[2] = fmaf(wgt, f.x, acc[2]); acc[3] = fmaf(wgt, f.y, acc[3]);
        f = __half22float2(*reinterpret_cast<__half2*>(&r.z));
        acc[4] = fmaf(wgt, f.x, acc[4]); acc[5] = fmaf(wgt, f.y, acc[5]);
        f = __half22float2(*reinterpret_cast<__half2*>(&r.w));
        acc[6] = fmaf(wgt, f.x, acc[6]); acc[7] = fmaf(wgt, f.y, acc[7]);
    }

    den += __shfl_xor_sync(0xffffffffu, den, 16);
    #pragma unroll
    for (int j = 0; j < 8; j++)
        acc[j] += __shfl_xor_sync(0xffffffffu, acc[j], 16);

    float inv = 1.f / (den + 1e-16f);
    #pragma unroll
    for (int j = 0; j < 8; j++) acc[j] *= inv;

    float other[8];
    #pragma unroll
    for (int j = 0; j < 8; j++)
        other[j] = __shfl_xor_sync(0xffffffffu, acc[j], 8);

    if (grp == 0 && hsel == 0) {
        float4 r0 = make_float4(0.5f * (acc[0] + other[0]), 0.5f * (acc[1] + other[1]),
                                0.5f * (acc[2] + other[2]), 0.5f * (acc[3] + other[3]));
        float4 r1 = make_float4(0.5f * (acc[4] + other[4]), 0.5f * (acc[5] + other[5]),
                                0.5f * (acc[6] + other[6]), 0.5f * (acc[7] + other[7]));
        float* dst = ta + (size_t)t * 128 + layer * 64 + sub * 8;
        *(float4*)(dst)     = r0;
        *(float4*)(dst + 4) = r1;
    }
}

// ---------------- head: tanh-attention fusion + FC + log_softmax ------------
__global__ __launch_bounds__(256)
void head_kernel(const float* __restrict__ u, const float* __restrict__ v,
                 const float* __restrict__ ta,
                 const float* __restrict__ aam, const float* __restrict__ fcw,
                 const float* __restrict__ fcb, float* __restrict__ outp)
{
    int w    = (blockIdx.x * blockDim.x + threadIdx.x) >> 5;
    int lane = threadIdx.x & 31;
    if (w >= NUSER) return;
    int d1 = lane, d2 = lane + 32;

    float u1   = u[w * 64 + d1],            u2   = u[w * 64 + d2];
    float v01  = v[(2*w) * 64 + d1],        v02  = v[(2*w) * 64 + d2];
    float v11  = v[(2*w+1) * 64 + d1],      v12  = v[(2*w+1) * 64 + d2];
    float ta01 = ta[w * 128 + d1],          ta02 = ta[w * 128 + d2];
    float ta11 = ta[w * 128 + 64 + d1],     ta12 = ta[w * 128 + 64 + d2];
    float am1  = __ldg(aam + d1),           am2  = __ldg(aam + d2);

    float s0 = tanhf(u1 + v01) * am1 + tanhf(u2 + v02) * am2;
    float s1 = tanhf(u1 + v11) * am1 + tanhf(u2 + v12) * am2;
    #pragma unroll
    for (int o = 16; o > 0; o >>= 1) {
        s0 += __shfl_xor_sync(0xffffffffu, s0, o);
        s1 += __shfl_xor_sync(0xffffffffu, s1, o);
    }
    float m  = fmaxf(s0, s1);
    float e0 = expf(s0 - m), e1 = expf(s1 - m);
    float rb = 1.f / (e0 + e1);
    float b0 = e0 * rb, b1 = e1 * rb;

    float f1 = b0 * ta01 + b1 * ta11;
    float f2 = b0 * ta02 + b1 * ta12;

    float l0 = ta01 * __ldg(fcw + d1)        + ta02 * __ldg(fcw + d2)
             + ta11 * __ldg(fcw + 64 + d1)   + ta12 * __ldg(fcw + 64 + d2)
             + f1   * __ldg(fcw + 128 + d1)  + f2   * __ldg(fcw + 128 + d2);
    float l1 = ta01 * __ldg(fcw + 192 + d1)  + ta02 * __ldg(fcw + 192 + d2)
             + ta11 * __ldg(fcw + 256 + d1)  + ta12 * __ldg(fcw + 256 + d2)
             + f1   * __ldg(fcw + 320 + d1)  + f2   * __ldg(fcw + 320 + d2);
    #pragma unroll
    for (int o = 16; o > 0; o >>= 1) {
        l0 += __shfl_xor_sync(0xffffffffu, l0, o);
        l1 += __shfl_xor_sync(0xffffffffu, l1, o);
    }
    if (lane == 0) {
        l0 += __ldg(fcb + 0);
        l1 += __ldg(fcb + 1);
        float mm  = fmaxf(l0, l1);
        float lse = mm + logf(expf(l0 - mm) + expf(l1 - mm));
        outp[w * 2]     = l0 - lse;
        outp[w * 2 + 1] = l1 - lse;
    }
}

// ---------------- launch ----------------------------------------------------
extern "C" void kernel_launch(void* const* d_in, const int* in_sizes, int n_in,
                              void* d_out, int out_size)
{
    const float* h     = (const float*)d_in[0];
    const int*   src0  = (const int*)  d_in[1];
    const int*   trg0  = (const int*)  d_in[2];
    const int*   src1  = (const int*)  d_in[3];
    const int*   trg1  = (const int*)  d_in[4];
    const float* w0    = (const float*)d_in[5];
    const float* asrc0 = (const float*)d_in[6];
    const float* atrg0 = (const float*)d_in[7];
    const float* w1    = (const float*)d_in[8];
    const float* asrc1 = (const float*)d_in[9];
    const float* atrg1 = (const float*)d_in[10];
    const float* aaw1  = (const float*)d_in[11];
    const float* aaw2  = (const float*)d_in[12];
    const float* aam   = (const float*)d_in[13];
    const float* fcw   = (const float*)d_in[14];
    const float* fcb   = (const float*)d_in[15];
    float* out = (float*)d_out;

    __half *hp0, *hp1;
    float *as_, *at_, *ta, *u, *v;
    int *cnt, *off, *cur, *part, *csr;
    cudaGetSymbolAddress((void**)&hp0,  g_hp0);
    cudaGetSymbolAddress((void**)&hp1,  g_hp1);
    cudaGetSymbolAddress((void**)&as_,  g_as);
    cudaGetSymbolAddress((void**)&at_,  g_at);
    cudaGetSymbolAddress((void**)&ta,   g_ta);
    cudaGetSymbolAddress((void**)&u,    g_u);
    cudaGetSymbolAddress((void**)&v,    g_v);
    cudaGetSymbolAddress((void**)&cnt,  g_cnt);
    cudaGetSymbolAddress((void**)&off,  g_off);
    cudaGetSymbolAddress((void**)&cur,  g_cur);
    cudaGetSymbolAddress((void**)&part, g_part);
    cudaGetSymbolAddress((void**)&csr,  g_csr);

    const int SM128 = (64 * 132 + 64 * 128) * 4;   // 66560 B
    const int SM64  = (64 * 132 + 64 * 64)  * 4;   // 50176 B
    cudaFuncSetAttribute(gemm_hp_fused, cudaFuncAttributeMaxDynamicSharedMemorySize, SM128);
    cudaFuncSetAttribute(gemm_head,     cudaFuncAttributeMaxDynamicSharedMemorySize, SM64);

    const int EDGE2_BLK = (2 * N_EDGES + 255) / 256;   // 12500
    const int GATH_BLK  = (NT2 * 32 + 255) / 256;      // 22500
    const int HEAD_BLK  = NUSER * 32 / 256;            // 11250

    // CSR build (cnt is zero: zero-init at load, reset by gather each replay)
    hist_kernel<<<EDGE2_BLK, 256>>>(trg0, trg1, cnt);
    scan1_kernel<<<NPART, 256>>>(cnt, off, part);
    scan23_kernel<<<NPART, 256>>>(off, part, cur);
    scatter_kernel<<<EDGE2_BLK, 256>>>(src0, trg0, src1, trg1, cur, csr);

    // hp GEMMs (both layers) with fused attention logits
    dim3 ggrid((N_NODES + 127) / 128, 2);
    gemm_hp_fused<<<ggrid, 256, SM128>>>(h, w0, w1, asrc0, atrg0, asrc1, atrg1,
                                         hp0, hp1, as_, at_, N_NODES);

    // gather both layers (resets cnt)
    gather_kernel<<<GATH_BLK, 256>>>(csr, off, cnt, as_, at_, hp0, hp1, ta);

    // head GEMMs (flat grid: u then v) + head
    gemm_head<<<UB + VB, 256, SM64>>>(h, aaw1, u, NUSER, ta, aaw2, v, NUSER * 2);
    head_kernel<<<HEAD_BLK, 256>>>(u, v, ta, aam, fcw, fcb, out);

    (void)in_sizes; (void)n_in; (void)out_size;
}

// round 10
// speedup vs baseline: 2.9173x; 2.2561x over previous
#include <cuda_runtime.h>
#include <cuda_fp16.h>
#include <math.h>

#define N_NODES 100000
#define N_EDGES 1600000
#define NUSER   90000
#define NT2     (2 * NUSER)            // merged bucket count = 180000
#define SCAN_CHUNK 1024
#define NPART   ((NT2 + SCAN_CHUNK - 1) / SCAN_CHUNK)   // 176

// ---------------- scratch (device globals; no allocation allowed) ----------
__device__ __align__(16) __half g_hp0[N_NODES * 128];
__device__ __align__(16) __half g_hp1[N_NODES * 128];
__device__ __align__(16) float g_as [2 * N_NODES * 2];  // [layer][n*2+h]
__device__ __align__(16) float g_at [2 * N_NODES * 2];
__device__ __align__(16) float g_ta [NUSER  * 128];     // type_aware (n, k, d)
__device__ __align__(16) float g_u  [NUSER  * 64];
__device__ __align__(16) float g_v  [NUSER  * 128];
__device__ __align__(16) int   g_cnt[NT2];              // counts
__device__ __align__(16) int   g_off[NT2];              // CSR offsets
__device__ __align__(16) int   g_cur[NT2];              // scatter cursors
__device__ __align__(16) int   g_part[256];
__device__ __align__(16) int   g_csr[2 * N_EDGES];      // bucketed src ids

// ---------------- fused hp GEMM + attn logits -------------------------------
__global__ __launch_bounds__(256)
void gemm_hp_fused(const float* __restrict__ A,
                   const float* __restrict__ W0, const float* __restrict__ W1,
                   const float* __restrict__ asrc0, const float* __restrict__ atrg0,
                   const float* __restrict__ asrc1, const float* __restrict__ atrg1,
                   __half* __restrict__ hp0, __half* __restrict__ hp1,
                   float* __restrict__ asOut, float* __restrict__ atOut, int M)
{
    constexpr int P   = 128;
    constexpr int BM  = 128;
    constexpr int LDA = BM + 4;

    const int layer = blockIdx.y;
    const float* Braw = layer ? W1 : W0;
    const float* aS   = layer ? asrc1 : asrc0;
    const float* aT   = layer ? atrg1 : atrg0;
    __half* hpL = layer ? hp1 : hp0;

    extern __shared__ float smem[];
    float* As = smem;                        // [64][LDA]
    float* Bs = smem + 64 * LDA;             // [64][128]

    const int t    = threadIdx.x;
    const int row0 = blockIdx.x * BM;

    #pragma unroll 4
    for (int i = t; i < 64 * P; i += 256) {
        int kk = i >> 7, c = i & 127;
        Bs[kk * P + c] = Braw[(c >> 6) * 4096 + kk * 64 + (c & 63)];
    }
    #pragma unroll 4
    for (int i = t; i < BM * 16; i += 256) {
        int r  = i >> 4;
        int k4 = (i & 15) << 2;
        float4 a = make_float4(0.f, 0.f, 0.f, 0.f);
        if (row0 + r < M) a = *(const float4*)(A + (size_t)(row0 + r) * 64 + k4);
        As[(k4 + 0) * LDA + r] = a.x;
        As[(k4 + 1) * LDA + r] = a.y;
        As[(k4 + 2) * LDA + r] = a.z;
        As[(k4 + 3) * LDA + r] = a.w;
    }
    __syncthreads();

    const int cg = t & 15;
    const int rg = t >> 4;

    float acc[8][8];
    #pragma unroll
    for (int r = 0; r < 8; r++)
        #pragma unroll
        for (int c = 0; c < 8; c++) acc[r][c] = 0.f;

    #pragma unroll
    for (int k = 0; k < 64; k++) {
        float4 a0 = *(const float4*)(As + k * LDA + rg * 8);
        float4 a1 = *(const float4*)(As + k * LDA + rg * 8 + 4);
        float a[8] = {a0.x, a0.y, a0.z, a0.w, a1.x, a1.y, a1.z, a1.w};
        float4 b0 = *(const float4*)(Bs + k * P + cg * 8);
        float4 b1 = *(const float4*)(Bs + k * P + cg * 8 + 4);
        float b[8] = {b0.x, b0.y, b0.z, b0.w, b1.x, b1.y, b1.z, b1.w};
        #pragma unroll
        for (int r = 0; r < 8; r++)
            #pragma unroll
            for (int c = 0; c < 8; c++)
                acc[r][c] = fmaf(a[r], b[c], acc[r][c]);
    }

    #pragma unroll
    for (int r = 0; r < 8; r++) {
        int row = row0 + rg * 8 + r;
        if (row < M) {
            union { __half2 h2[4]; uint4 u4; } pk;
            #pragma unroll
            for (int c2 = 0; c2 < 4; c2++)
                pk.h2[c2] = __floats2half2_rn(acc[r][2*c2], acc[r][2*c2+1]);
            *(uint4*)(hpL + (size_t)row * 128 + cg * 8) = pk.u4;
        }
    }

    float4 s0 = *(const float4*)(aS + cg * 8);
    float4 s1 = *(const float4*)(aS + cg * 8 + 4);
    float4 t0 = *(const float4*)(aT + cg * 8);
    float4 t1 = *(const float4*)(aT + cg * 8 + 4);
    float sv[8] = {s0.x, s0.y, s0.z, s0.w, s1.x, s1.y, s1.z, s1.w};
    float tv[8] = {t0.x, t0.y, t0.z, t0.w, t1.x, t1.y, t1.z, t1.w};

    float pas[8], pat[8];
    #pragma unroll
    for (int r = 0; r < 8; r++) {
        float a_ = 0.f, b_ = 0.f;
        #pragma unroll
        for (int c = 0; c < 8; c++) {
            a_ = fmaf(acc[r][c], sv[c], a_);
            b_ = fmaf(acc[r][c], tv[c], b_);
        }
        pas[r] = a_; pat[r] = b_;
    }
    #pragma unroll
    for (int o = 1; o < 8; o <<= 1) {
        #pragma unroll
        for (int r = 0; r < 8; r++) {
            pas[r] += __shfl_xor_sync(0xffffffffu, pas[r], o);
            pat[r] += __shfl_xor_sync(0xffffffffu, pat[r], o);
        }
    }
    if ((cg & 7) == 0) {
        int head  = cg >> 3;
        int abase = layer * N_NODES * 2;
        #pragma unroll
        for (int r = 0; r < 8; r++) {
            int row = row0 + rg * 8 + r;
            if (row < M) {
                asOut[abase + row * 2 + head] = pas[r];
                atOut[abase + row * 2 + head] = pat[r];
            }
        }
    }
}

// ---------------- head GEMMs merged: y=0 -> u = h@aaw1^T ; y=1 -> v = ta@aaw2^T
__global__ __launch_bounds__(256)
void gemm_head(const float* __restrict__ A0, const float* __restrict__ B0,
               float* __restrict__ C0, int M0,
               const float* __restrict__ A1, const float* __restrict__ B1,
               float* __restrict__ C1, int M1)
{
    constexpr int P   = 64;
    constexpr int BM  = 128;
    constexpr int LDA = BM + 4;

    const int sel = blockIdx.y;
    const float* A    = sel ? A1 : A0;
    const float* Braw = sel ? B1 : B0;
    float*       C    = sel ? C1 : C0;
    const int    M    = sel ? M1 : M0;

    const int row0 = blockIdx.x * BM;
    if (row0 >= M) return;

    extern __shared__ float smem[];
    float* As = smem;
    float* Bs = smem + 64 * LDA;

    const int t = threadIdx.x;

    #pragma unroll 4
    for (int i = t; i < 64 * P; i += 256) {
        int kk = i / P, c = i % P;
        Bs[kk * P + c] = Braw[c * 64 + kk];
    }
    #pragma unroll 4
    for (int i = t; i < BM * 16; i += 256) {
        int r  = i >> 4;
        int k4 = (i & 15) << 2;
        float4 a = make_float4(0.f, 0.f, 0.f, 0.f);
        if (row0 + r < M) a = *(const float4*)(A + (size_t)(row0 + r) * 64 + k4);
        As[(k4 + 0) * LDA + r] = a.x;
        As[(k4 + 1) * LDA + r] = a.y;
        As[(k4 + 2) * LDA + r] = a.z;
        As[(k4 + 3) * LDA + r] = a.w;
    }
    __syncthreads();

    const int cg = t & 15;
    const int rg = t >> 4;

    float acc[8][4];
    #pragma unroll
    for (int r = 0; r < 8; r++)
        #pragma unroll
        for (int c = 0; c < 4; c++) acc[r][c] = 0.f;

    #pragma unroll
    for (int k = 0; k < 64; k++) {
        float4 a0 = *(const float4*)(As + k * LDA + rg * 8);
        float4 a1 = *(const float4*)(As + k * LDA + rg * 8 + 4);
        float a[8] = {a0.x, a0.y, a0.z, a0.w, a1.x, a1.y, a1.z, a1.w};
        float4 b0 = *(const float4*)(Bs + k * P + cg * 4);
        float b[4] = {b0.x, b0.y, b0.z, b0.w};
        #pragma unroll
        for (int r = 0; r < 8; r++)
            #pragma unroll
            for (int c = 0; c < 4; c++)
                acc[r][c] = fmaf(a[r], b[c], acc[r][c]);
    }

    #pragma unroll
    for (int r = 0; r < 8; r++) {
        int row = row0 + rg * 8 + r;
        if (row < M) {
            float4 o = make_float4(acc[r][0], acc[r][1], acc[r][2], acc[r][3]);
            *(float4*)(C + (size_t)row * P + cg * 4) = o;
        }
    }
}

// ---------------- CSR build --------------------------------------------------
__global__ void zero_cnt_kernel(int* __restrict__ cnt)
{
    int i = blockIdx.x * blockDim.x + threadIdx.x;
    if (i < NT2) cnt[i] = 0;
}

__global__ __launch_bounds__(256)
void hist_kernel(const int* __restrict__ trgA, const int* __restrict__ trgB,
                 int* __restrict__ cnt)
{
    int i = blockIdx.x * blockDim.x + threadIdx.x;
    if (i >= 2 * N_EDGES) return;
    int layer = (i >= N_EDGES);
    const int* trg = layer ? trgB : trgA;
    int t = __ldg(trg + (i - layer * N_EDGES));
    if (t < NUSER) atomicAdd(cnt + layer * NUSER + t, 1);
}

__global__ __launch_bounds__(256)
void scan1_kernel(const int* __restrict__ cnt, int* __restrict__ off,
                  int* __restrict__ part)
{
    __shared__ int s[256];
    int t = threadIdx.x, b = blockIdx.x;
    int i0 = b * SCAN_CHUNK + t * 4;
    int c[4];
    #pragma unroll
    for (int j = 0; j < 4; j++) c[j] = (i0 + j < NT2) ? cnt[i0 + j] : 0;
    int tot = c[0] + c[1] + c[2] + c[3];
    s[t] = tot;
    __syncthreads();
    int v = s[t];
    #pragma unroll
    for (int o = 1; o < 256; o <<= 1) {
        int u = (t >= o) ? s[t - o] : 0;
        __syncthreads();
        v += u; s[t] = v;
        __syncthreads();
    }
    int excl = v - tot;
    #pragma unroll
    for (int j = 0; j < 4; j++) {
        if (i0 + j < NT2) off[i0 + j] = excl;
        excl += c[j];
    }
    if (t == 255) part[b] = v;
}

__global__ void scan2_kernel(int* __restrict__ part)
{
    __shared__ int s[256];
    int t = threadIdx.x;
    int own = (t < NPART) ? part[t] : 0;
    s[t] = own;
    __syncthreads();
    int v = s[t];
    #pragma unroll
    for (int o = 1; o < 256; o <<= 1) {
        int u = (t >= o) ? s[t - o] : 0;
        __syncthreads();
        v += u; s[t] = v;
        __syncthreads();
    }
    if (t < NPART) part[t] = v - own;
}

// add chunk base AND initialize scatter cursor
__global__ void scan3_kernel(int* __restrict__ off, const int* __restrict__ part,
                             int* __restrict__ cur)
{
    int i = blockIdx.x * blockDim.x + threadIdx.x;
    if (i < NT2) {
        int o = off[i] + part[i / SCAN_CHUNK];
        off[i] = o;
        cur[i] = o;
    }
}

__global__ __launch_bounds__(256)
void scatter_kernel(const int* __restrict__ srcA, const int* __restrict__ trgA,
                    const int* __restrict__ srcB, const int* __restrict__ trgB,
                    int* __restrict__ cur, int* __restrict__ csr)
{
    int i = blockIdx.x * blockDim.x + threadIdx.x;
    if (i >= 2 * N_EDGES) return;
    int layer = (i >= N_EDGES);
    int e = i - layer * N_EDGES;
    const int* trg = layer ? trgB : trgA;
    const int* src = layer ? srcB : srcA;
    int t = __ldg(trg + e);
    if (t >= NUSER) return;
    int pos = atomicAdd(cur + layer * NUSER + t, 1);
    csr[pos] = __ldg(src + e);
}

// ---------------- gather: warp per (layer, target), 2 edges/iter ------------
__global__ __launch_bounds__(256)
void gather_kernel(const int* __restrict__ csr, const int* __restrict__ off,
                   const int* __restrict__ cnt,
                   const float* __restrict__ as_, const float* __restrict__ at_,
                   const __half* __restrict__ hp0, const __half* __restrict__ hp1,
                   float* __restrict__ ta)
{
    int w    = (blockIdx.x * blockDim.x + threadIdx.x) >> 5;
    int lane = threadIdx.x & 31;
    if (w >= NT2) return;
    int layer = (w >= NUSER);
    int t = w - layer * NUSER;
    const __half* hpL = layer ? hp1 : hp0;
    int abase = layer * N_NODES * 2;

    int grp  = lane >> 4;        // which edge of the pair
    int sub  = lane & 15;        // 16-lane slot within edge
    int hsel = sub >> 3;         // head of this lane

    float at_own = __ldg(at_ + abase + 2 * t + hsel);
    int start = __ldg(off + w);
    int n     = __ldg(cnt + w);

    float acc[8];
    #pragma unroll
    for (int j = 0; j < 8; j++) acc[j] = 0.f;
    float den = 0.f;

    for (int i = 0; i < n; i += 2) {
        int idx = i + grp;
        bool valid = idx < n;
        int sidx = valid ? idx : i;
        int s = __ldg(csr + start + sidx);
        float e = __ldg(as_ + abase + 2 * s + hsel) + at_own;
        e = (e > 0.f) ? e : 0.2f * e;
        float wgt = valid ? __expf(e) : 0.f;
        den += wgt;
        uint4 r = *(const uint4*)(hpL + (size_t)s * 128 + sub * 8);
        float2 f;
        f = __half22float2(*reinterpret_cast<__half2*>(&r.x));
        acc[0] = fmaf(wgt, f.x, acc[0]); acc[1] = fmaf(wgt, f.y, acc[1]);
        f = __half22float2(*reinterpret_cast<__half2*>(&r.y));
        acc[2] = fmaf(wgt, f.x, acc[2]); acc[3] = fmaf(wgt, f.y, acc[3]);
        f = __half22float2(*reinterpret_cast<__half2*>(&r.z));
        acc[4] = fmaf(wgt, f.x, acc[4]); acc[5] = fmaf(wgt, f.y, acc[5]);
        f = __half22float2(*reinterpret_cast<__half2*>(&r.w));
        acc[6] = fmaf(wgt, f.x, acc[6]); acc[7] = fmaf(wgt, f.y, acc[7]);
    }

    den += __shfl_xor_sync(0xffffffffu, den, 16);
    #pragma unroll
    for (int j = 0; j < 8; j++)
        acc[j] += __shfl_xor_sync(0xffffffffu, acc[j], 16);

    float inv = 1.f / (den + 1e-16f);
    #pragma unroll
    for (int j = 0; j < 8; j++) acc[j] *= inv;

    float other[8];
    #pragma unroll
    for (int j = 0; j < 8; j++)
        other[j] = __shfl_xor_sync(0xffffffffu, acc[j], 8);

    if (grp == 0 && hsel == 0) {
        float4 r0 = make_float4(0.5f * (acc[0] + other[0]), 0.5f * (acc[1] + other[1]),
                                0.5f * (acc[2] + other[2]), 0.5f * (acc[3] + other[3]));
        float4 r1 = make_float4(0.5f * (acc[4] + other[4]), 0.5f * (acc[5] + other[5]),
                                0.5f * (acc[6] + other[6]), 0.5f * (acc[7] + other[7]));
        float* dst = ta + (size_t)t * 128 + layer * 64 + sub * 8;
        *(float4*)(dst)     = r0;
        *(float4*)(dst + 4) = r1;
    }
}

// ---------------- head: tanh-attention fusion + FC + log_softmax ------------
__global__ __launch_bounds__(256)
void head_kernel(const float* __restrict__ u, const float* __restrict__ v,
                 const float* __restrict__ ta,
                 const float* __restrict__ aam, const float* __restrict__ fcw,
                 const float* __restrict__ fcb, float* __restrict__ outp)
{
    int w    = (blockIdx.x * blockDim.x + threadIdx.x) >> 5;
    int lane = threadIdx.x & 31;
    if (w >= NUSER) return;
    int d1 = lane, d2 = lane + 32;

    float u1   = u[w * 64 + d1],            u2   = u[w * 64 + d2];
    float v01  = v[(2*w) * 64 + d1],        v02  = v[(2*w) * 64 + d2];
    float v11  = v[(2*w+1) * 64 + d1],      v12  = v[(2*w+1) * 64 + d2];
    float ta01 = ta[w * 128 + d1],          ta02 = ta[w * 128 + d2];
    float ta11 = ta[w * 128 + 64 + d1],     ta12 = ta[w * 128 + 64 + d2];
    float am1  = __ldg(aam + d1),           am2  = __ldg(aam + d2);

    float s0 = tanhf(u1 + v01) * am1 + tanhf(u2 + v02) * am2;
    float s1 = tanhf(u1 + v11) * am1 + tanhf(u2 + v12) * am2;
    #pragma unroll
    for (int o = 16; o > 0; o >>= 1) {
        s0 += __shfl_xor_sync(0xffffffffu, s0, o);
        s1 += __shfl_xor_sync(0xffffffffu, s1, o);
    }
    float m  = fmaxf(s0, s1);
    float e0 = expf(s0 - m), e1 = expf(s1 - m);
    float rb = 1.f / (e0 + e1);
    float b0 = e0 * rb, b1 = e1 * rb;

    float f1 = b0 * ta01 + b1 * ta11;
    float f2 = b0 * ta02 + b1 * ta12;

    float l0 = ta01 * __ldg(fcw + d1)        + ta02 * __ldg(fcw + d2)
             + ta11 * __ldg(fcw + 64 + d1)   + ta12 * __ldg(fcw + 64 + d2)
             + f1   * __ldg(fcw + 128 + d1)  + f2   * __ldg(fcw + 128 + d2);
    float l1 = ta01 * __ldg(fcw + 192 + d1)  + ta02 * __ldg(fcw + 192 + d2)
             + ta11 * __ldg(fcw + 256 + d1)  + ta12 * __ldg(fcw + 256 + d2)
             + f1   * __ldg(fcw + 320 + d1)  + f2   * __ldg(fcw + 320 + d2);
    #pragma unroll
    for (int o = 16; o > 0; o >>= 1) {
        l0 += __shfl_xor_sync(0xffffffffu, l0, o);
        l1 += __shfl_xor_sync(0xffffffffu, l1, o);
    }
    if (lane == 0) {
        l0 += __ldg(fcb + 0);
        l1 += __ldg(fcb + 1);
        float mm  = fmaxf(l0, l1);
        float lse = mm + logf(expf(l0 - mm) + expf(l1 - mm));
        outp[w * 2]     = l0 - lse;
        outp[w * 2 + 1] = l1 - lse;
    }
}

// ---------------- launch ----------------------------------------------------
extern "C" void kernel_launch(void* const* d_in, const int* in_sizes, int n_in,
                              void* d_out, int out_size)
{
    const float* h     = (const float*)d_in[0];
    const int*   src0  = (const int*)  d_in[1];
    const int*   trg0  = (const int*)  d_in[2];
    const int*   src1  = (const int*)  d_in[3];
    const int*   trg1  = (const int*)  d_in[4];
    const float* w0    = (const float*)d_in[5];
    const float* asrc0 = (const float*)d_in[6];
    const float* atrg0 = (const float*)d_in[7];
    const float* w1    = (const float*)d_in[8];
    const float* asrc1 = (const float*)d_in[9];
    const float* atrg1 = (const float*)d_in[10];
    const float* aaw1  = (const float*)d_in[11];
    const float* aaw2  = (const float*)d_in[12];
    const float* aam   = (const float*)d_in[13];
    const float* fcw   = (const float*)d_in[14];
    const float* fcb   = (const float*)d_in[15];
    float* out = (float*)d_out;

    __half *hp0, *hp1;
    float *as_, *at_, *ta, *u, *v;
    int *cnt, *off, *cur, *part, *csr;
    cudaGetSymbolAddress((void**)&hp0,  g_hp0);
    cudaGetSymbolAddress((void**)&hp1,  g_hp1);
    cudaGetSymbolAddress((void**)&as_,  g_as);
    cudaGetSymbolAddress((void**)&at_,  g_at);
    cudaGetSymbolAddress((void**)&ta,   g_ta);
    cudaGetSymbolAddress((void**)&u,    g_u);
    cudaGetSymbolAddress((void**)&v,    g_v);
    cudaGetSymbolAddress((void**)&cnt,  g_cnt);
    cudaGetSymbolAddress((void**)&off,  g_off);
    cudaGetSymbolAddress((void**)&cur,  g_cur);
    cudaGetSymbolAddress((void**)&part, g_part);
    cudaGetSymbolAddress((void**)&csr,  g_csr);

    const int SM128 = (64 * 132 + 64 * 128) * 4;
    const int SM64  = (64 * 132 + 64 * 64)  * 4;
    cudaFuncSetAttribute(gemm_hp_fused, cudaFuncAttributeMaxDynamicSharedMemorySize, SM128);
    cudaFuncSetAttribute(gemm_head,     cudaFuncAttributeMaxDynamicSharedMemorySize, SM64);

    const int EDGE2_BLK = (2 * N_EDGES + 255) / 256;
    const int GATH_BLK  = (NT2 * 32 + 255) / 256;
    const int HEAD_BLK  = NUSER * 32 / 256;

    // CSR build for both layers
    zero_cnt_kernel<<<(NT2 + 255) / 256, 256>>>(cnt);
    hist_kernel<<<EDGE2_BLK, 256>>>(trg0, trg1, cnt);
    scan1_kernel<<<NPART, 256>>>(cnt, off, part);
    scan2_kernel<<<1, 256>>>(part);
    scan3_kernel<<<(NT2 + 255) / 256, 256>>>(off, part, cur);
    scatter_kernel<<<EDGE2_BLK, 256>>>(src0, trg0, src1, trg1, cur, csr);

    // hp GEMMs (both layers) with fused attention logits
    dim3 ggrid((N_NODES + 127) / 128, 2);
    gemm_hp_fused<<<ggrid, 256, SM128>>>(h, w0, w1, asrc0, atrg0, asrc1, atrg1,
                                         hp0, hp1, as_, at_, N_NODES);

    // gather both layers
    gather_kernel<<<GATH_BLK, 256>>>(csr, off, cnt, as_, at_, hp0, hp1, ta);

    // head GEMMs (merged) + head
    dim3 hgrid((NUSER * 2 + 127) / 128, 2);
    gemm_head<<<hgrid, 256, SM64>>>(h, aaw1, u, NUSER, ta, aaw2, v, NUSER * 2);
    head_kernel<<<HEAD_BLK, 256>>>(u, v, ta, aam, fcw, fcb, out);

    (void)in_sizes; (void)n_in; (void)out_size;
}

// round 11
// speedup vs baseline: 2.9941x; 1.0263x over previous
#include <cuda_runtime.h>
#include <cuda_fp16.h>
#include <math.h>

#define N_NODES 100000
#define N_EDGES 1600000
#define NUSER   90000
#define NT2     (2 * NUSER)            // merged bucket count = 180000
#define SCAN_CHUNK 1024
#define NPART   ((NT2 + SCAN_CHUNK - 1) / SCAN_CHUNK)   // 176

// ---------------- scratch (device globals; no allocation allowed) ----------
__device__ __align__(16) __half g_hp0[N_NODES * 128];
__device__ __align__(16) __half g_hp1[N_NODES * 128];
__device__ __align__(16) float g_as [2 * N_NODES * 2];  // [layer][n*2+h]
__device__ __align__(16) float g_at [2 * N_NODES * 2];
__device__ __align__(16) float g_ta [NUSER  * 128];     // type_aware (n, k, d)
__device__ __align__(16) float g_u  [NUSER  * 64];
__device__ __align__(16) float g_v  [NUSER  * 128];
__device__ __align__(16) int   g_cnt[NT2];              // counts
__device__ __align__(16) int   g_off[NT2];              // CSR offsets
__device__ __align__(16) int   g_cur[NT2];              // scatter cursors
__device__ __align__(16) int   g_part[256];
__device__ __align__(16) int   g_csr[2 * N_EDGES];      // bucketed src ids

// ---------------- fused hp GEMM + attn logits -------------------------------
__global__ __launch_bounds__(256)
void gemm_hp_fused(const float* __restrict__ A,
                   const float* __restrict__ W0, const float* __restrict__ W1,
                   const float* __restrict__ asrc0, const float* __restrict__ atrg0,
                   const float* __restrict__ asrc1, const float* __restrict__ atrg1,
                   __half* __restrict__ hp0, __half* __restrict__ hp1,
                   float* __restrict__ asOut, float* __restrict__ atOut, int M)
{
    constexpr int P   = 128;
    constexpr int BM  = 128;
    constexpr int LDA = BM + 4;

    const int layer = blockIdx.y;
    const float* Braw = layer ? W1 : W0;
    const float* aS   = layer ? asrc1 : asrc0;
    const float* aT   = layer ? atrg1 : atrg0;
    __half* hpL = layer ? hp1 : hp0;

    extern __shared__ float smem[];
    float* As = smem;                        // [64][LDA]
    float* Bs = smem + 64 * LDA;             // [64][128]

    const int t    = threadIdx.x;
    const int row0 = blockIdx.x * BM;

    #pragma unroll 4
    for (int i = t; i < 64 * P; i += 256) {
        int kk = i >> 7, c = i & 127;
        Bs[kk * P + c] = Braw[(c >> 6) * 4096 + kk * 64 + (c & 63)];
    }
    #pragma unroll 4
    for (int i = t; i < BM * 16; i += 256) {
        int r  = i >> 4;
        int k4 = (i & 15) << 2;
        float4 a = make_float4(0.f, 0.f, 0.f, 0.f);
        if (row0 + r < M) a = *(const float4*)(A + (size_t)(row0 + r) * 64 + k4);
        As[(k4 + 0) * LDA + r] = a.x;
        As[(k4 + 1) * LDA + r] = a.y;
        As[(k4 + 2) * LDA + r] = a.z;
        As[(k4 + 3) * LDA + r] = a.w;
    }
    __syncthreads();

    const int cg = t & 15;
    const int rg = t >> 4;

    float acc[8][8];
    #pragma unroll
    for (int r = 0; r < 8; r++)
        #pragma unroll
        for (int c = 0; c < 8; c++) acc[r][c] = 0.f;

    #pragma unroll
    for (int k = 0; k < 64; k++) {
        float4 a0 = *(const float4*)(As + k * LDA + rg * 8);
        float4 a1 = *(const float4*)(As + k * LDA + rg * 8 + 4);
        float a[8] = {a0.x, a0.y, a0.z, a0.w, a1.x, a1.y, a1.z, a1.w};
        float4 b0 = *(const float4*)(Bs + k * P + cg * 8);
        float4 b1 = *(const float4*)(Bs + k * P + cg * 8 + 4);
        float b[8] = {b0.x, b0.y, b0.z, b0.w, b1.x, b1.y, b1.z, b1.w};
        #pragma unroll
        for (int r = 0; r < 8; r++)
            #pragma unroll
            for (int c = 0; c < 8; c++)
                acc[r][c] = fmaf(a[r], b[c], acc[r][c]);
    }

    #pragma unroll
    for (int r = 0; r < 8; r++) {
        int row = row0 + rg * 8 + r;
        if (row < M) {
            union { __half2 h2[4]; uint4 u4; } pk;
            #pragma unroll
            for (int c2 = 0; c2 < 4; c2++)
                pk.h2[c2] = __floats2half2_rn(acc[r][2*c2], acc[r][2*c2+1]);
            *(uint4*)(hpL + (size_t)row * 128 + cg * 8) = pk.u4;
        }
    }

    float4 s0 = *(const float4*)(aS + cg * 8);
    float4 s1 = *(const float4*)(aS + cg * 8 + 4);
    float4 t0 = *(const float4*)(aT + cg * 8);
    float4 t1 = *(const float4*)(aT + cg * 8 + 4);
    float sv[8] = {s0.x, s0.y, s0.z, s0.w, s1.x, s1.y, s1.z, s1.w};
    float tv[8] = {t0.x, t0.y, t0.z, t0.w, t1.x, t1.y, t1.z, t1.w};

    float pas[8], pat[8];
    #pragma unroll
    for (int r = 0; r < 8; r++) {
        float a_ = 0.f, b_ = 0.f;
        #pragma unroll
        for (int c = 0; c < 8; c++) {
            a_ = fmaf(acc[r][c], sv[c], a_);
            b_ = fmaf(acc[r][c], tv[c], b_);
        }
        pas[r] = a_; pat[r] = b_;
    }
    #pragma unroll
    for (int o = 1; o < 8; o <<= 1) {
        #pragma unroll
        for (int r = 0; r < 8; r++) {
            pas[r] += __shfl_xor_sync(0xffffffffu, pas[r], o);
            pat[r] += __shfl_xor_sync(0xffffffffu, pat[r], o);
        }
    }
    if ((cg & 7) == 0) {
        int head  = cg >> 3;
        int abase = layer * N_NODES * 2;
        #pragma unroll
        for (int r = 0; r < 8; r++) {
            int row = row0 + rg * 8 + r;
            if (row < M) {
                asOut[abase + row * 2 + head] = pas[r];
                atOut[abase + row * 2 + head] = pat[r];
            }
        }
    }
}

// ---------------- head GEMMs merged: y=0 -> u = h@aaw1^T ; y=1 -> v = ta@aaw2^T
__global__ __launch_bounds__(256)
void gemm_head(const float* __restrict__ A0, const float* __restrict__ B0,
               float* __restrict__ C0, int M0,
               const float* __restrict__ A1, const float* __restrict__ B1,
               float* __restrict__ C1, int M1)
{
    constexpr int P   = 64;
    constexpr int BM  = 128;
    constexpr int LDA = BM + 4;

    const int sel = blockIdx.y;
    const float* A    = sel ? A1 : A0;
    const float* Braw = sel ? B1 : B0;
    float*       C    = sel ? C1 : C0;
    const int    M    = sel ? M1 : M0;

    const int row0 = blockIdx.x * BM;
    if (row0 >= M) return;

    extern __shared__ float smem[];
    float* As = smem;
    float* Bs = smem + 64 * LDA;

    const int t = threadIdx.x;

    #pragma unroll 4
    for (int i = t; i < 64 * P; i += 256) {
        int kk = i / P, c = i % P;
        Bs[kk * P + c] = Braw[c * 64 + kk];
    }
    #pragma unroll 4
    for (int i = t; i < BM * 16; i += 256) {
        int r  = i >> 4;
        int k4 = (i & 15) << 2;
        float4 a = make_float4(0.f, 0.f, 0.f, 0.f);
        if (row0 + r < M) a = *(const float4*)(A + (size_t)(row0 + r) * 64 + k4);
        As[(k4 + 0) * LDA + r] = a.x;
        As[(k4 + 1) * LDA + r] = a.y;
        As[(k4 + 2) * LDA + r] = a.z;
        As[(k4 + 3) * LDA + r] = a.w;
    }
    __syncthreads();

    const int cg = t & 15;
    const int rg = t >> 4;

    float acc[8][4];
    #pragma unroll
    for (int r = 0; r < 8; r++)
        #pragma unroll
        for (int c = 0; c < 4; c++) acc[r][c] = 0.f;

    #pragma unroll
    for (int k = 0; k < 64; k++) {
        float4 a0 = *(const float4*)(As + k * LDA + rg * 8);
        float4 a1 = *(const float4*)(As + k * LDA + rg * 8 + 4);
        float a[8] = {a0.x, a0.y, a0.z, a0.w, a1.x, a1.y, a1.z, a1.w};
        float4 b0 = *(const float4*)(Bs + k * P + cg * 4);
        float b[4] = {b0.x, b0.y, b0.z, b0.w};
        #pragma unroll
        for (int r = 0; r < 8; r++)
            #pragma unroll
            for (int c = 0; c < 4; c++)
                acc[r][c] = fmaf(a[r], b[c], acc[r][c]);
    }

    #pragma unroll
    for (int r = 0; r < 8; r++) {
        int row = row0 + rg * 8 + r;
        if (row < M) {
            float4 o = make_float4(acc[r][0], acc[r][1], acc[r][2], acc[r][3]);
            *(float4*)(C + (size_t)row * P + cg * 4) = o;
        }
    }
}

// ---------------- CSR build --------------------------------------------------
__global__ void zero_cnt_kernel(int* __restrict__ cnt)
{
    int i = blockIdx.x * blockDim.x + threadIdx.x;
    if (i < NT2) cnt[i] = 0;
}

__global__ __launch_bounds__(256)
void hist_kernel(const int* __restrict__ trgA, const int* __restrict__ trgB,
                 int* __restrict__ cnt)
{
    int i = blockIdx.x * blockDim.x + threadIdx.x;
    if (i >= 2 * N_EDGES) return;
    int layer = (i >= N_EDGES);
    const int* trg = layer ? trgB : trgA;
    int t = __ldg(trg + (i - layer * N_EDGES));
    if (t < NUSER) atomicAdd(cnt + layer * NUSER + t, 1);
}

__global__ __launch_bounds__(256)
void scan1_kernel(const int* __restrict__ cnt, int* __restrict__ off,
                  int* __restrict__ part)
{
    __shared__ int s[256];
    int t = threadIdx.x, b = blockIdx.x;
    int i0 = b * SCAN_CHUNK + t * 4;
    int c[4];
    #pragma unroll
    for (int j = 0; j < 4; j++) c[j] = (i0 + j < NT2) ? cnt[i0 + j] : 0;
    int tot = c[0] + c[1] + c[2] + c[3];
    s[t] = tot;
    __syncthreads();
    int v = s[t];
    #pragma unroll
    for (int o = 1; o < 256; o <<= 1) {
        int u = (t >= o) ? s[t - o] : 0;
        __syncthreads();
        v += u; s[t] = v;
        __syncthreads();
    }
    int excl = v - tot;
    #pragma unroll
    for (int j = 0; j < 4; j++) {
        if (i0 + j < NT2) off[i0 + j] = excl;
        excl += c[j];
    }
    if (t == 255) part[b] = v;
}

__global__ void scan2_kernel(int* __restrict__ part)
{
    __shared__ int s[256];
    int t = threadIdx.x;
    int own = (t < NPART) ? part[t] : 0;
    s[t] = own;
    __syncthreads();
    int v = s[t];
    #pragma unroll
    for (int o = 1; o < 256; o <<= 1) {
        int u = (t >= o) ? s[t - o] : 0;
        __syncthreads();
        v += u; s[t] = v;
        __syncthreads();
    }
    if (t < NPART) part[t] = v - own;
}

// add chunk base AND initialize scatter cursor
__global__ void scan3_kernel(int* __restrict__ off, const int* __restrict__ part,
                             int* __restrict__ cur)
{
    int i = blockIdx.x * blockDim.x + threadIdx.x;
    if (i < NT2) {
        int o = off[i] + part[i / SCAN_CHUNK];
        off[i] = o;
        cur[i] = o;
    }
}

__global__ __launch_bounds__(256)
void scatter_kernel(const int* __restrict__ srcA, const int* __restrict__ trgA,
                    const int* __restrict__ srcB, const int* __restrict__ trgB,
                    int* __restrict__ cur, int* __restrict__ csr)
{
    int i = blockIdx.x * blockDim.x + threadIdx.x;
    if (i >= 2 * N_EDGES) return;
    int layer = (i >= N_EDGES);
    int e = i - layer * N_EDGES;
    const int* trg = layer ? trgB : trgA;
    const int* src = layer ? srcB : srcA;
    int t = __ldg(trg + e);
    if (t >= NUSER) return;
    int pos = atomicAdd(cur + layer * NUSER + t, 1);
    csr[pos] = __ldg(src + e);
}

// ---------------- gather: warp per (layer, target), unrolled x2 -------------
// lanes [0,16) -> even edge of pair, lanes [16,32) -> odd.
// Main loop: 4 edges in flight (two independent csr->as_->hp chains per group).
__global__ __launch_bounds__(256)
void gather_kernel(const int* __restrict__ csr, const int* __restrict__ off,
                   const int* __restrict__ cnt,
                   const float* __restrict__ as_, const float* __restrict__ at_,
                   const __half* __restrict__ hp0, const __half* __restrict__ hp1,
                   float* __restrict__ ta)
{
    int w    = (blockIdx.x * blockDim.x + threadIdx.x) >> 5;
    int lane = threadIdx.x & 31;
    if (w >= NT2) return;
    int layer = (w >= NUSER);
    int t = w - layer * NUSER;
    const __half* hpL = layer ? hp1 : hp0;
    int abase = layer * N_NODES * 2;

    int grp  = lane >> 4;        // which edge of the pair
    int sub  = lane & 15;        // 16-lane slot within edge
    int hsel = sub >> 3;         // head of this lane

    float at_own = __ldg(at_ + abase + 2 * t + hsel);
    int start = __ldg(off + w);
    int n     = __ldg(cnt + w);

    float acc[8];
    #pragma unroll
    for (int j = 0; j < 8; j++) acc[j] = 0.f;
    float den = 0.f;

    int i = 0;
    // main loop: both chains unconditionally valid
    for (; i + 4 <= n; i += 4) {
        int sA = __ldg(csr + start + i + grp);
        int sB = __ldg(csr + start + i + 2 + grp);
        float eA = __ldg(as_ + abase + 2 * sA + hsel) + at_own;
        float eB = __ldg(as_ + abase + 2 * sB + hsel) + at_own;
        eA = (eA > 0.f) ? eA : 0.2f * eA;
        eB = (eB > 0.f) ? eB : 0.2f * eB;
        float wA = __expf(eA);
        float wB = __expf(eB);
        uint4 rA = *(const uint4*)(hpL + (size_t)sA * 128 + sub * 8);
        uint4 rB = *(const uint4*)(hpL + (size_t)sB * 128 + sub * 8);
        den += wA + wB;
        float2 f;
        f = __half22float2(*reinterpret_cast<__half2*>(&rA.x));
        acc[0] = fmaf(wA, f.x, acc[0]); acc[1] = fmaf(wA, f.y, acc[1]);
        f = __half22float2(*reinterpret_cast<__half2*>(&rA.y));
        acc[2] = fmaf(wA, f.x, acc[2]); acc[3] = fmaf(wA, f.y, acc[3]);
        f = __half22float2(*reinterpret_cast<__half2*>(&rA.z));
        acc[4] = fmaf(wA, f.x, acc[4]); acc[5] = fmaf(wA, f.y, acc[5]);
        f = __half22float2(*reinterpret_cast<__half2*>(&rA.w));
        acc[6] = fmaf(wA, f.x, acc[6]); acc[7] = fmaf(wA, f.y, acc[7]);
        f = __half22float2(*reinterpret_cast<__half2*>(&rB.x));
        acc[0] = fmaf(wB, f.x, acc[0]); acc[1] = fmaf(wB, f.y, acc[1]);
        f = __half22float2(*reinterpret_cast<__half2*>(&rB.y));
        acc[2] = fmaf(wB, f.x, acc[2]); acc[3] = fmaf(wB, f.y, acc[3]);
        f = __half22float2(*reinterpret_cast<__half2*>(&rB.z));
        acc[4] = fmaf(wB, f.x, acc[4]); acc[5] = fmaf(wB, f.y, acc[5]);
        f = __half22float2(*reinterpret_cast<__half2*>(&rB.w));
        acc[6] = fmaf(wB, f.x, acc[6]); acc[7] = fmaf(wB, f.y, acc[7]);
    }
    // tail: 2 edges per iteration with validity predicate
    for (; i < n; i += 2) {
        int idx = i + grp;
        bool valid = idx < n;
        int sidx = valid ? idx : i;
        int s = __ldg(csr + start + sidx);
        float e = __ldg(as_ + abase + 2 * s + hsel) + at_own;
        e = (e > 0.f) ? e : 0.2f * e;
        float wgt = valid ? __expf(e) : 0.f;
        den += wgt;
        uint4 r = *(const uint4*)(hpL + (size_t)s * 128 + sub * 8);
        float2 f;
        f = __half22float2(*reinterpret_cast<__half2*>(&r.x));
        acc[0] = fmaf(wgt, f.x, acc[0]); acc[1] = fmaf(wgt, f.y, acc[1]);
        f = __half22float2(*reinterpret_cast<__half2*>(&r.y));
        acc[2] = fmaf(wgt, f.x, acc[2]); acc[3] = fmaf(wgt, f.y, acc[3]);
        f = __half22float2(*reinterpret_cast<__half2*>(&r.z));
        acc[4] = fmaf(wgt, f.x, acc[4]); acc[5] = fmaf(wgt, f.y, acc[5]);
        f = __half22float2(*reinterpret_cast<__half2*>(&r.w));
        acc[6] = fmaf(wgt, f.x, acc[6]); acc[7] = fmaf(wgt, f.y, acc[7]);
    }

    den += __shfl_xor_sync(0xffffffffu, den, 16);
    #pragma unroll
    for (int j = 0; j < 8; j++)
        acc[j] += __shfl_xor_sync(0xffffffffu, acc[j], 16);

    float inv = 1.f / (den + 1e-16f);
    #pragma unroll
    for (int j = 0; j < 8; j++) acc[j] *= inv;

    float other[8];
    #pragma unroll
    for (int j = 0; j < 8; j++)
        other[j] = __shfl_xor_sync(0xffffffffu, acc[j], 8);

    if (grp == 0 && hsel == 0) {
        float4 r0 = make_float4(0.5f * (acc[0] + other[0]), 0.5f * (acc[1] + other[1]),
                                0.5f * (acc[2] + other[2]), 0.5f * (acc[3] + other[3]));
        float4 r1 = make_float4(0.5f * (acc[4] + other[4]), 0.5f * (acc[5] + other[5]),
                                0.5f * (acc[6] + other[6]), 0.5f * (acc[7] + other[7]));
        float* dst = ta + (size_t)t * 128 + layer * 64 + sub * 8;
        *(float4*)(dst)     = r0;
        *(float4*)(dst + 4) = r1;
    }
}

// ---------------- head: tanh-attention fusion + FC + log_softmax ------------
__global__ __launch_bounds__(256)
void head_kernel(const float* __restrict__ u, const float* __restrict__ v,
                 const float* __restrict__ ta,
                 const float* __restrict__ aam, const float* __restrict__ fcw,
                 const float* __restrict__ fcb, float* __restrict__ outp)
{
    int w    = (blockIdx.x * blockDim.x + threadIdx.x) >> 5;
    int lane = threadIdx.x & 31;
    if (w >= NUSER) return;
    int d1 = lane, d2 = lane + 32;

    float u1   = u[w * 64 + d1],            u2   = u[w * 64 + d2];
    float v01  = v[(2*w) * 64 + d1],        v02  = v[(2*w) * 64 + d2];
    float v11  = v[(2*w+1) * 64 + d1],      v12  = v[(2*w+1) * 64 + d2];
    float ta01 = ta[w * 128 + d1],          ta02 = ta[w * 128 + d2];
    float ta11 = ta[w * 128 + 64 + d1],     ta12 = ta[w * 128 + 64 + d2];
    float am1  = __ldg(aam + d1),           am2  = __ldg(aam + d2);

    float s0 = tanhf(u1 + v01) * am1 + tanhf(u2 + v02) * am2;
    float s1 = tanhf(u1 + v11) * am1 + tanhf(u2 + v12) * am2;
    #pragma unroll
    for (int o = 16; o > 0; o >>= 1) {
        s0 += __shfl_xor_sync(0xffffffffu, s0, o);
        s1 += __shfl_xor_sync(0xffffffffu, s1, o);
    }
    float m  = fmaxf(s0, s1);
    float e0 = expf(s0 - m), e1 = expf(s1 - m);
    float rb = 1.f / (e0 + e1);
    float b0 = e0 * rb, b1 = e1 * rb;

    float f1 = b0 * ta01 + b1 * ta11;
    float f2 = b0 * ta02 + b1 * ta12;

    float l0 = ta01 * __ldg(fcw + d1)        + ta02 * __ldg(fcw + d2)
             + ta11 * __ldg(fcw + 64 + d1)   + ta12 * __ldg(fcw + 64 + d2)
             + f1   * __ldg(fcw + 128 + d1)  + f2   * __ldg(fcw + 128 + d2);
    float l1 = ta01 * __ldg(fcw + 192 + d1)  + ta02 * __ldg(fcw + 192 + d2)
             + ta11 * __ldg(fcw + 256 + d1)  + ta12 * __ldg(fcw + 256 + d2)
             + f1   * __ldg(fcw + 320 + d1)  + f2   * __ldg(fcw + 320 + d2);
    #pragma unroll
    for (int o = 16; o > 0; o >>= 1) {
        l0 += __shfl_xor_sync(0xffffffffu, l0, o);
        l1 += __shfl_xor_sync(0xffffffffu, l1, o);
    }
    if (lane == 0) {
        l0 += __ldg(fcb + 0);
        l1 += __ldg(fcb + 1);
        float mm  = fmaxf(l0, l1);
        float lse = mm + logf(expf(l0 - mm) + expf(l1 - mm));
        outp[w * 2]     = l0 - lse;
        outp[w * 2 + 1] = l1 - lse;
    }
}

// ---------------- launch ----------------------------------------------------
extern "C" void kernel_launch(void* const* d_in, const int* in_sizes, int n_in,
                              void* d_out, int out_size)
{
    const float* h     = (const float*)d_in[0];
    const int*   src0  = (const int*)  d_in[1];
    const int*   trg0  = (const int*)  d_in[2];
    const int*   src1  = (const int*)  d_in[3];
    const int*   trg1  = (const int*)  d_in[4];
    const float* w0    = (const float*)d_in[5];
    const float* asrc0 = (const float*)d_in[6];
    const float* atrg0 = (const float*)d_in[7];
    const float* w1    = (const float*)d_in[8];
    const float* asrc1 = (const float*)d_in[9];
    const float* atrg1 = (const float*)d_in[10];
    const float* aaw1  = (const float*)d_in[11];
    const float* aaw2  = (const float*)d_in[12];
    const float* aam   = (const float*)d_in[13];
    const float* fcw   = (const float*)d_in[14];
    const float* fcb   = (const float*)d_in[15];
    float* out = (float*)d_out;

    __half *hp0, *hp1;
    float *as_, *at_, *ta, *u, *v;
    int *cnt, *off, *cur, *part, *csr;
    cudaGetSymbolAddress((void**)&hp0,  g_hp0);
    cudaGetSymbolAddress((void**)&hp1,  g_hp1);
    cudaGetSymbolAddress((void**)&as_,  g_as);
    cudaGetSymbolAddress((void**)&at_,  g_at);
    cudaGetSymbolAddress((void**)&ta,   g_ta);
    cudaGetSymbolAddress((void**)&u,    g_u);
    cudaGetSymbolAddress((void**)&v,    g_v);
    cudaGetSymbolAddress((void**)&cnt,  g_cnt);
    cudaGetSymbolAddress((void**)&off,  g_off);
    cudaGetSymbolAddress((void**)&cur,  g_cur);
    cudaGetSymbolAddress((void**)&part, g_part);
    cudaGetSymbolAddress((void**)&csr,  g_csr);

    const int SM128 = (64 * 132 + 64 * 128) * 4;
    const int SM64  = (64 * 132 + 64 * 64)  * 4;
    cudaFuncSetAttribute(gemm_hp_fused, cudaFuncAttributeMaxDynamicSharedMemorySize, SM128);
    cudaFuncSetAttribute(gemm_head,     cudaFuncAttributeMaxDynamicSharedMemorySize, SM64);

    const int EDGE2_BLK = (2 * N_EDGES + 255) / 256;
    const int GATH_BLK  = (NT2 * 32 + 255) / 256;
    const int HEAD_BLK  = NUSER * 32 / 256;

    // CSR build for both layers
    zero_cnt_kernel<<<(NT2 + 255) / 256, 256>>>(cnt);
    hist_kernel<<<EDGE2_BLK, 256>>>(trg0, trg1, cnt);
    scan1_kernel<<<NPART, 256>>>(cnt, off, part);
    scan2_kernel<<<1, 256>>>(part);
    scan3_kernel<<<(NT2 + 255) / 256, 256>>>(off, part, cur);
    scatter_kernel<<<EDGE2_BLK, 256>>>(src0, trg0, src1, trg1, cur, csr);

    // hp GEMMs (both layers) with fused attention logits
    dim3 ggrid((N_NODES + 127) / 128, 2);
    gemm_hp_fused<<<ggrid, 256, SM128>>>(h, w0, w1, asrc0, atrg0, asrc1, atrg1,
                                         hp0, hp1, as_, at_, N_NODES);

    // gather both layers
    gather_kernel<<<GATH_BLK, 256>>>(csr, off, cnt, as_, at_, hp0, hp1, ta);

    // head GEMMs (merged) + head
    dim3 hgrid((NUSER * 2 + 127) / 128, 2);
    gemm_head<<<hgrid, 256, SM64>>>(h, aaw1, u, NUSER, ta, aaw2, v, NUSER * 2);
    head_kernel<<<HEAD_BLK, 256>>>(u, v, ta, aam, fcw, fcb, out);

    (void)in_sizes; (void)n_in; (void)out_size;
}